// round 13
// baseline (speedup 1.0000x reference)
#include <cuda_runtime.h>
#include <cuda_bf16.h>
#include <math.h>
#include <stdint.h>

#define T_TOK 4096
#define D_DIM 768
#define N_ST  16
#define E_EXP 4
#define DFF_F 3072
#define V_VOC 32000
#define NLYR  4
#define BSZ   2
#define SEQL  2048
#define NPK   832      // packed delta|B|C width: 768 + 16 + 16 + 32 pad
#define KSPL  4        // split-K factor for MoE down

// ---------------- scratch ----------------
__device__ float g_h[T_TOK * D_DIM];
__device__ float g_delta[T_TOK * D_DIM];
__device__ float g_Bm[T_TOK * N_ST];
__device__ float g_Cm[T_TOK * N_ST];
__device__ float g_y[T_TOK * D_DIM];
__device__ float g_part[KSPL * T_TOK * D_DIM];
__device__ float g_H[T_TOK * DFF_F];
__device__ float g_w[T_TOK];
__device__ int   g_eid[T_TOK];
__device__ int   g_pos[T_TOK];
__device__ int   g_perm[T_TOK];
__device__ int   g_cnt[E_EXP];
__device__ float g_Wpack[NLYR * D_DIM * NPK];
__device__ float g_bpack[NLYR * NPK];
__device__ __nv_bfloat16 g_eH[V_VOC * D_DIM];
__device__ __nv_bfloat16 g_eL[V_VOC * D_DIM];
__device__ __nv_bfloat16 g_hH[T_TOK * D_DIM];
__device__ __nv_bfloat16 g_hL[T_TOK * D_DIM];

// ---------------- helpers ----------------
__device__ __forceinline__ uint32_t smem_u32(const void* p) {
    uint32_t a;
    asm("{ .reg .u64 t; cvta.to.shared.u64 t, %1; cvt.u32.u64 %0, t; }" : "=r"(a) : "l"(p));
    return a;
}
__device__ __forceinline__ void cp16(uint32_t s, const void* g) {
    asm volatile("cp.async.cg.shared.global [%0], [%1], 16;" :: "r"(s), "l"(g));
}
#define CP_COMMIT() asm volatile("cp.async.commit_group;" ::: "memory")
#define CP_WAIT1()  asm volatile("cp.async.wait_group 1;" ::: "memory")
#define CP_WAIT0()  asm volatile("cp.async.wait_group 0;" ::: "memory")

#define LDSM4(R0,R1,R2,R3,ADDR) \
    asm volatile("ldmatrix.sync.aligned.m8n8.x4.shared.b16 {%0,%1,%2,%3}, [%4];" \
        : "=r"(R0),"=r"(R1),"=r"(R2),"=r"(R3) : "r"(ADDR))
#define LDSM4T(R0,R1,R2,R3,ADDR) \
    asm volatile("ldmatrix.sync.aligned.m8n8.x4.trans.shared.b16 {%0,%1,%2,%3}, [%4];" \
        : "=r"(R0),"=r"(R1),"=r"(R2),"=r"(R3) : "r"(ADDR))
#define MMA_BF16(D,AV,BV) \
    asm volatile("mma.sync.aligned.m16n8k16.row.col.f32.bf16.bf16.f32 " \
        "{%0,%1,%2,%3}, {%4,%5,%6,%7}, {%8,%9}, {%0,%1,%2,%3};" \
        : "+f"((D)[0]),"+f"((D)[1]),"+f"((D)[2]),"+f"((D)[3]) \
        : "r"((AV)[0]),"r"((AV)[1]),"r"((AV)[2]),"r"((AV)[3]), \
          "r"((BV)[0]),"r"((BV)[1]))

__device__ __forceinline__ void splt(float v, uint32_t& h, uint32_t& l) {
    __nv_bfloat16 bh = __float2bfloat16(v);
    float r = v - __bfloat162float(bh);
    __nv_bfloat16 bl = __float2bfloat16(r);
    h = (uint32_t)__bfloat16_as_ushort(bh);
    l = (uint32_t)__bfloat16_as_ushort(bl);
}
__device__ __forceinline__ void split_pack(float a, float b, uint32_t& hp, uint32_t& lp) {
    uint32_t h0, l0, h1, l1;
    splt(a, h0, l0); splt(b, h1, l1);
    hp = h0 | (h1 << 16);
    lp = l0 | (l1 << 16);
}

// ---------------- embed gather ----------------
__global__ void embed_gather_k(const int* __restrict__ x,
                               const float* __restrict__ embed,
                               float* __restrict__ h) {
    int t = blockIdx.x;
    int tok = x[t];
    const float4* src = (const float4*)(embed + (size_t)tok * D_DIM);
    float4* dst = (float4*)(h + (size_t)t * D_DIM);
    dst[threadIdx.x] = src[threadIdx.x];
}

// ---------------- fp32 -> split-bf16 planes ----------------
__global__ void split_k(const float* __restrict__ s,
                        __nv_bfloat16* __restrict__ hi,
                        __nv_bfloat16* __restrict__ lo) {
    size_t i = ((size_t)blockIdx.x * 256 + threadIdx.x) * 4;
    float4 v = *(const float4*)(s + i);
    uint32_t hp0, lp0, hp1, lp1;
    split_pack(v.x, v.y, hp0, lp0);
    split_pack(v.z, v.w, hp1, lp1);
    *(uint2*)(hi + i) = make_uint2(hp0, hp1);
    *(uint2*)(lo + i) = make_uint2(lp0, lp1);
}

// ---------------- pack [Wd|WB|WC] -> [768, 832] fp32 + biases ----------------
__global__ void pack_k(const float* __restrict__ Wd, const float* __restrict__ WB,
                       const float* __restrict__ WC,
                       const float* __restrict__ bd, const float* __restrict__ bB,
                       const float* __restrict__ bC,
                       float* __restrict__ Wp, float* __restrict__ bp) {
    int i = (blockIdx.x * 256 + threadIdx.x) * 4;
    int k = i / NPK, c = i % NPK;
#pragma unroll
    for (int j = 0; j < 4; j++) {
        int c2 = c + j;
        float v;
        if (c2 < 768)      v = Wd[k * D_DIM + c2];
        else if (c2 < 784) v = WB[k * N_ST + c2 - 768];
        else if (c2 < 800) v = WC[k * N_ST + c2 - 784];
        else               v = 0.f;
        Wp[i + j] = v;
    }
    if (blockIdx.x == 0) {
        for (int c2 = threadIdx.x; c2 < NPK; c2 += 256) {
            float v;
            if (c2 < 768)      v = bd[c2];
            else if (c2 < 784) v = bB[c2 - 768];
            else if (c2 < 800) v = bC[c2 - 784];
            else               v = 0.f;
            bp[c2] = v;
        }
    }
}

#define PA 40   // A smem pitch in bf16
#define PB 72   // B smem pitch (k-major) in bf16

// ---------------- logits GEMM v2 (proven) ----------------
#define LG_SMEM 81920

__global__ void __launch_bounds__(256, 2) logits_v2(
    const __nv_bfloat16* __restrict__ hH, const __nv_bfloat16* __restrict__ hL,
    const __nv_bfloat16* __restrict__ eH, const __nv_bfloat16* __restrict__ eL,
    float* __restrict__ out)
{
    extern __shared__ char dsm[];
    const uint32_t sb = smem_u32(dsm);
    const int tid = threadIdx.x;
    const int bm = blockIdx.x * 128;
    const int bn = blockIdx.y * 128;

    const int w = tid >> 5, lane = tid & 31;
    const int wm = (w >> 1) * 32, wn = (w & 1) * 64;

    const int lrow = tid >> 1;
    const int lsegB = (tid & 1) * 32;
    const int lsegE = (tid & 1) * 16;
    const uint32_t sRow = (uint32_t)(lrow * 80 + lsegB);

#define LG_ISSUE(C) do {                                                        \
    const int k0_ = (C) * 32;                                                   \
    const uint32_t s0_ = sb + ((C) & 1) * 40960;                                \
    const __nv_bfloat16* g_;                                                    \
    g_ = hH + (size_t)(bm + lrow) * D_DIM + k0_ + lsegE;                        \
    cp16(s0_ + sRow, g_); cp16(s0_ + sRow + 16, g_ + 8);                        \
    g_ = hL + (size_t)(bm + lrow) * D_DIM + k0_ + lsegE;                        \
    cp16(s0_ + 10240 + sRow, g_); cp16(s0_ + 10240 + sRow + 16, g_ + 8);        \
    g_ = eH + (size_t)(bn + lrow) * D_DIM + k0_ + lsegE;                        \
    cp16(s0_ + 20480 + sRow, g_); cp16(s0_ + 20480 + sRow + 16, g_ + 8);        \
    g_ = eL + (size_t)(bn + lrow) * D_DIM + k0_ + lsegE;                        \
    cp16(s0_ + 30720 + sRow, g_); cp16(s0_ + 30720 + sRow + 16, g_ + 8);        \
    CP_COMMIT(); } while (0)

    const uint32_t a_off = (uint32_t)((lane & 15) * (PA * 2) + ((lane >> 4) & 1) * 16);
    uint32_t aB[2];
#pragma unroll
    for (int mi = 0; mi < 2; mi++) aB[mi] = (uint32_t)((wm + mi * 16) * (PA * 2)) + a_off;

    const uint32_t b_off = (uint32_t)(((lane & 7) + ((lane >> 4) & 1) * 8) * (PA * 2)
                                      + ((lane >> 3) & 1) * 16);
    uint32_t bB[4];
#pragma unroll
    for (int j = 0; j < 4; j++) bB[j] = (uint32_t)((wn + j * 16) * (PA * 2)) + b_off;

    float acc[2][8][4];
#pragma unroll
    for (int mi = 0; mi < 2; mi++)
#pragma unroll
        for (int nj = 0; nj < 8; nj++)
#pragma unroll
            for (int q = 0; q < 4; q++) acc[mi][nj][q] = 0.f;

    LG_ISSUE(0);
    LG_ISSUE(1);

    const int NC = D_DIM / 32;
    for (int c = 0; c < NC; c++) {
        if (c + 1 < NC) { CP_WAIT1(); } else { CP_WAIT0(); }
        __syncthreads();
        const uint32_t base = sb + (c & 1) * 40960;
#pragma unroll
        for (int kk = 0; kk < 32; kk += 16) {
            uint32_t ah[2][4], al[2][4], bh[8][2], bl[8][2];
#pragma unroll
            for (int mi = 0; mi < 2; mi++) {
                LDSM4(ah[mi][0], ah[mi][1], ah[mi][2], ah[mi][3], base + aB[mi] + kk * 2);
                LDSM4(al[mi][0], al[mi][1], al[mi][2], al[mi][3],
                      base + 10240 + aB[mi] + kk * 2);
            }
#pragma unroll
            for (int j = 0; j < 4; j++) {
                uint32_t r0, r1, r2, r3;
                LDSM4(r0, r1, r2, r3, base + 20480 + bB[j] + kk * 2);
                bh[2 * j][0] = r0; bh[2 * j][1] = r1;
                bh[2 * j + 1][0] = r2; bh[2 * j + 1][1] = r3;
                LDSM4(r0, r1, r2, r3, base + 30720 + bB[j] + kk * 2);
                bl[2 * j][0] = r0; bl[2 * j][1] = r1;
                bl[2 * j + 1][0] = r2; bl[2 * j + 1][1] = r3;
            }
#pragma unroll
            for (int mi = 0; mi < 2; mi++)
#pragma unroll
                for (int nj = 0; nj < 8; nj++) {
                    MMA_BF16(acc[mi][nj], ah[mi], bh[nj]);
                    MMA_BF16(acc[mi][nj], ah[mi], bl[nj]);
                    MMA_BF16(acc[mi][nj], al[mi], bh[nj]);
                }
        }
        __syncthreads();
        if (c + 2 < NC) LG_ISSUE(c + 2);
    }

#pragma unroll
    for (int mi = 0; mi < 2; mi++) {
#pragma unroll
        for (int half = 0; half < 2; half++) {
            int row = bm + wm + mi * 16 + (lane >> 2) + half * 8;
            float* orow = out + (size_t)row * V_VOC + bn + wn;
#pragma unroll
            for (int nj = 0; nj < 8; nj++) {
                int col = nj * 8 + (lane & 3) * 2;
                *(float2*)(orow + col) =
                    make_float2(acc[mi][nj][half * 2], acc[mi][nj][half * 2 + 1]);
            }
        }
    }
}

// ---------------- mma.sync GEMM (in-loop split-bf16 convert) ----------------
// MODE 2: MoE up gather rows (bias+silu)
// MODE 4: fused delta|B|C: dense A, packed B (N=832), region epilogue
// MODE 5: MoE down split-K: z = e*KSPL+ks; partial out, no bias/act
template<int MODE, int ACT>
__global__ void __launch_bounds__(256) gemm_tc(
    const float* __restrict__ A, const float* __restrict__ B,
    const float* __restrict__ bias, float* __restrict__ C,
    int N, int K,
    const int* __restrict__ perm, const float* __restrict__ wsc,
    const int* __restrict__ cnt,
    float* __restrict__ BmOut, float* __restrict__ CmOut)
{
    __shared__ __align__(16) __nv_bfloat16 Ah[128 * PA], Al[128 * PA];
    __shared__ __align__(16) __nv_bfloat16 Bh[2560], Bl[2560];

    const int tid = threadIdx.x;
    const int bn = blockIdx.x * 64;
    const int bm = blockIdx.y * 128;

    int cnt_e = 0, off_e = 0, ks = 0;
    if (MODE == 2 || MODE == 5) {
        int e = (MODE == 5) ? (blockIdx.z >> 2) : blockIdx.z;
        if (MODE == 5) ks = blockIdx.z & 3;
        cnt_e = cnt[e];
        for (int q = 0; q < E_EXP; q++) if (q < e) off_e += cnt[q];
        if (bm >= cnt_e) return;
        if (MODE == 2) {
            B += (size_t)e * K * N;
            bias += (size_t)e * N;
        } else {
            B += ((size_t)e * DFF_F + (size_t)ks * (DFF_F / KSPL)) * N;
        }
    }

    const int ar = tid >> 3;
    const int ac = (tid & 7) * 4;
    const float* arow[4];
#pragma unroll
    for (int i = 0; i < 4; i++) {
        int g = bm + ar + 32 * i;
        if (MODE == 4) arow[i] = A + (size_t)g * K;
        else if (MODE == 2) arow[i] = (g < cnt_e) ? A + (size_t)perm[off_e + g] * K : nullptr;
        else arow[i] = (g < cnt_e)
            ? A + (size_t)(off_e + g) * DFF_F + (size_t)ks * (DFF_F / KSPL) : nullptr;
    }
    const int bkr = tid >> 4;
    const int bbc = (tid & 15) * 4;

    const int w = tid >> 5, lane = tid & 31;
    const int wm = (w >> 1) * 32, wn = (w & 1) * 32;
    const uint32_t sAh = (uint32_t)__cvta_generic_to_shared(Ah);
    const uint32_t sAl = (uint32_t)__cvta_generic_to_shared(Al);
    const uint32_t sBh = (uint32_t)__cvta_generic_to_shared(Bh);
    const uint32_t sBl = (uint32_t)__cvta_generic_to_shared(Bl);

    const uint32_t a_off = (uint32_t)((lane & 15) * (PA * 2) + ((lane >> 4) & 1) * 16);
    uint32_t aBase[2];
#pragma unroll
    for (int mi = 0; mi < 2; mi++)
        aBase[mi] = (uint32_t)((wm + mi * 16) * (PA * 2)) + a_off;

    uint32_t bBase[2];
    {
        uint32_t b_off = (uint32_t)((lane & 15) * (PB * 2) + ((lane >> 4) & 1) * 16);
#pragma unroll
        for (int ni2 = 0; ni2 < 2; ni2++)
            bBase[ni2] = (uint32_t)((wn + ni2 * 16) * 2) + b_off;
    }

    float acc[2][4][4];
#pragma unroll
    for (int mi = 0; mi < 2; mi++)
#pragma unroll
        for (int nj = 0; nj < 4; nj++)
#pragma unroll
            for (int q = 0; q < 4; q++) acc[mi][nj][q] = 0.f;

    float4 av[4], bv[2];

#define LOAD_G(K0) do {                                                          \
    _Pragma("unroll")                                                            \
    for (int i = 0; i < 4; i++)                                                  \
        av[i] = arow[i] ? *(const float4*)(arow[i] + (K0) + ac)                  \
                        : make_float4(0.f, 0.f, 0.f, 0.f);                       \
    _Pragma("unroll")                                                            \
    for (int i = 0; i < 2; i++)                                                  \
        bv[i] = *(const float4*)(B + (size_t)((K0) + bkr + 16 * i) * N + bn + bbc); \
    } while (0)

#define STORE_S() do {                                                           \
    _Pragma("unroll")                                                            \
    for (int i = 0; i < 4; i++) {                                                \
        int row = ar + 32 * i;                                                   \
        uint32_t h0, l0, h1, l1;                                                 \
        split_pack(av[i].x, av[i].y, h0, l0);                                    \
        split_pack(av[i].z, av[i].w, h1, l1);                                    \
        uint32_t* pH = (uint32_t*)(Ah + row * PA + ac);                          \
        uint32_t* pL = (uint32_t*)(Al + row * PA + ac);                          \
        pH[0] = h0; pH[1] = h1; pL[0] = l0; pL[1] = l1;                          \
    }                                                                            \
    _Pragma("unroll")                                                            \
    for (int i = 0; i < 2; i++) {                                                \
        uint32_t h0, l0, h1, l1;                                                 \
        split_pack(bv[i].x, bv[i].y, h0, l0);                                    \
        split_pack(bv[i].z, bv[i].w, h1, l1);                                    \
        uint32_t* pH = (uint32_t*)(Bh + (bkr + 16 * i) * PB + bbc);              \
        uint32_t* pL = (uint32_t*)(Bl + (bkr + 16 * i) * PB + bbc);              \
        pH[0] = h0; pH[1] = h1; pL[0] = l0; pL[1] = l1;                          \
    } } while (0)

    LOAD_G(0);
    for (int k0 = 0; k0 < K; k0 += 32) {
        STORE_S();
        __syncthreads();
        if (k0 + 32 < K) LOAD_G(k0 + 32);

#pragma unroll
        for (int kk = 0; kk < 32; kk += 16) {
            uint32_t ah[2][4], alr[2][4], bhf[4][2], blf[4][2];
#pragma unroll
            for (int mi = 0; mi < 2; mi++) {
                LDSM4(ah[mi][0], ah[mi][1], ah[mi][2], ah[mi][3], sAh + aBase[mi] + kk * 2);
                LDSM4(alr[mi][0], alr[mi][1], alr[mi][2], alr[mi][3], sAl + aBase[mi] + kk * 2);
            }
#pragma unroll
            for (int ni2 = 0; ni2 < 2; ni2++) {
                uint32_t r0, r1, r2, r3;
                LDSM4T(r0, r1, r2, r3, sBh + bBase[ni2] + kk * (PB * 2));
                bhf[2 * ni2][0] = r0; bhf[2 * ni2][1] = r1;
                bhf[2 * ni2 + 1][0] = r2; bhf[2 * ni2 + 1][1] = r3;
                LDSM4T(r0, r1, r2, r3, sBl + bBase[ni2] + kk * (PB * 2));
                blf[2 * ni2][0] = r0; blf[2 * ni2][1] = r1;
                blf[2 * ni2 + 1][0] = r2; blf[2 * ni2 + 1][1] = r3;
            }
#pragma unroll
            for (int mi = 0; mi < 2; mi++)
#pragma unroll
                for (int nj = 0; nj < 4; nj++) {
                    MMA_BF16(acc[mi][nj], ah[mi], bhf[nj]);
                    MMA_BF16(acc[mi][nj], ah[mi], blf[nj]);
                    MMA_BF16(acc[mi][nj], alr[mi], bhf[nj]);
                }
        }
        __syncthreads();
    }

#pragma unroll
    for (int mi = 0; mi < 2; mi++) {
#pragma unroll
        for (int half = 0; half < 2; half++) {
            int tr = wm + mi * 16 + (lane >> 2) + half * 8;
            int g = bm + tr;
            size_t orow = (size_t)g;
            bool valid = true;
            if (MODE == 2) { valid = g < cnt_e; orow = (size_t)(off_e + g); }
            else if (MODE == 5) {
                valid = g < cnt_e;
                int tok = valid ? perm[off_e + g] : 0;
                orow = (size_t)ks * T_TOK + tok;
            }
            if (!valid) continue;
#pragma unroll
            for (int nj = 0; nj < 4; nj++) {
                int col = bn + wn + nj * 8 + (lane & 3) * 2;
                float u0 = acc[mi][nj][half * 2 + 0];
                float u1 = acc[mi][nj][half * 2 + 1];
                if (MODE == 5) {
                    *(float2*)(C + orow * (size_t)N + col) = make_float2(u0, u1);
                    continue;
                }
                float2 bb = *(const float2*)&bias[col];
                u0 += bb.x; u1 += bb.y;
                if (MODE == 4) {
                    if (col < 768) {
                        u0 = fmaxf(u0, 0.f) + log1pf(expf(-fabsf(u0)));
                        u1 = fmaxf(u1, 0.f) + log1pf(expf(-fabsf(u1)));
                        *(float2*)(C + orow * (size_t)D_DIM + col) = make_float2(u0, u1);
                    } else if (col < 784) {
                        *(float2*)(BmOut + orow * (size_t)N_ST + col - 768) = make_float2(u0, u1);
                    } else if (col < 800) {
                        *(float2*)(CmOut + orow * (size_t)N_ST + col - 784) = make_float2(u0, u1);
                    }
                    continue;
                }
                if (ACT == 2) {
                    u0 = u0 / (1.f + __expf(-u0));
                    u1 = u1 / (1.f + __expf(-u1));
                }
                *(float2*)(C + orow * (size_t)N + col) = make_float2(u0, u1);
            }
        }
    }
}

// ---------------- SSM scan: 2 chains per thread (ILP x2) ----------------
// grid (D/16, B), 128 threads: 8 d-groups x 16 n-lanes, each thread runs
// chains for d = d0+dg and d = d0+dg+8.
__global__ void __launch_bounds__(128) scan_k(
    const float* __restrict__ h, const float* __restrict__ delta,
    const float* __restrict__ Bm, const float* __restrict__ Cm,
    const float* __restrict__ A_log, const float* __restrict__ Dp,
    float* __restrict__ y, int* __restrict__ cnt)
{
    const int b  = blockIdx.y;
    const int d0 = blockIdx.x * 16;
    const int tid = threadIdx.x;
    const int dg = tid >> 4;      // 0..7
    const int n  = tid & 15;
    const int dA = d0 + dg;
    const int dBc = d0 + dg + 8;

    if (blockIdx.x == 0 && b == 0 && tid < E_EXP) cnt[tid] = 0;

    const float a0 = -expf(A_log[dA * N_ST + n]);
    const float a1 = -expf(A_log[dBc * N_ST + n]);
    const float Dv0 = Dp[dA];
    const float Dv1 = Dp[dBc];
    float hs0 = 0.f, hs1 = 0.f;

    __shared__ float xs[2][16][16], ds[2][16][16];
    __shared__ float bs[2][16][16], cs[2][16][16];

    const int lt = tid >> 3;      // 0..15 (time row)
    const int ld = tid & 7;       // 0..7  (col; also col+8)
    const size_t tok0 = (size_t)b * SEQL;

    xs[0][lt][ld]     = h[(tok0 + lt) * D_DIM + d0 + ld];
    xs[0][lt][ld + 8] = h[(tok0 + lt) * D_DIM + d0 + ld + 8];
    ds[0][lt][ld]     = delta[(tok0 + lt) * D_DIM + d0 + ld];
    ds[0][lt][ld + 8] = delta[(tok0 + lt) * D_DIM + d0 + ld + 8];
    bs[0][lt][ld]     = Bm[(tok0 + lt) * N_ST + ld];
    bs[0][lt][ld + 8] = Bm[(tok0 + lt) * N_ST + ld + 8];
    cs[0][lt][ld]     = Cm[(tok0 + lt) * N_ST + ld];
    cs[0][lt][ld + 8] = Cm[(tok0 + lt) * N_ST + ld + 8];
    __syncthreads();

    const int NCH = SEQL / 16;
    for (int c = 0; c < NCH; c++) {
        int buf = c & 1;
        float px0 = 0.f, px1 = 0.f, pd0 = 0.f, pd1 = 0.f;
        float pb0 = 0.f, pb1 = 0.f, pc0 = 0.f, pc1 = 0.f;
        bool has = (c + 1) < NCH;
        if (has) {
            size_t t1 = tok0 + (c + 1) * 16 + lt;
            px0 = h[t1 * D_DIM + d0 + ld];
            px1 = h[t1 * D_DIM + d0 + ld + 8];
            pd0 = delta[t1 * D_DIM + d0 + ld];
            pd1 = delta[t1 * D_DIM + d0 + ld + 8];
            pb0 = Bm[t1 * N_ST + ld];  pb1 = Bm[t1 * N_ST + ld + 8];
            pc0 = Cm[t1 * N_ST + ld];  pc1 = Cm[t1 * N_ST + ld + 8];
        }
        int tbase = c * 16;
#pragma unroll
        for (int s = 0; s < 16; s++) {
            float xv0 = xs[buf][s][dg];
            float xv1 = xs[buf][s][dg + 8];
            float dv0 = ds[buf][s][dg];
            float dv1 = ds[buf][s][dg + 8];
            float Bv = bs[buf][s][n];
            float Cv = cs[buf][s][n];
            float bA0 = __expf(fminf(dv0 * a0, 2.f));
            float bA1 = __expf(fminf(dv1 * a1, 2.f));
            float bB0 = fminf(fmaxf(dv0 * Bv, -2.f), 2.f);
            float bB1 = fminf(fmaxf(dv1 * Bv, -2.f), 2.f);
            hs0 = fminf(fmaxf(fmaf(bA0, hs0, bB0 * xv0), -100.f), 100.f);
            hs1 = fminf(fmaxf(fmaf(bA1, hs1, bB1 * xv1), -100.f), 100.f);
            float p0 = hs0 * Cv;
            float p1 = hs1 * Cv;
            p0 += __shfl_xor_sync(0xffffffffu, p0, 1, 16);
            p1 += __shfl_xor_sync(0xffffffffu, p1, 1, 16);
            p0 += __shfl_xor_sync(0xffffffffu, p0, 2, 16);
            p1 += __shfl_xor_sync(0xffffffffu, p1, 2, 16);
            p0 += __shfl_xor_sync(0xffffffffu, p0, 4, 16);
            p1 += __shfl_xor_sync(0xffffffffu, p1, 4, 16);
            p0 += __shfl_xor_sync(0xffffffffu, p0, 8, 16);
            p1 += __shfl_xor_sync(0xffffffffu, p1, 8, 16);
            if (n == 0) {
                size_t base = (tok0 + tbase + s) * D_DIM;
                y[base + dA]  = p0 + xv0 * Dv0;
                y[base + dBc] = p1 + xv1 * Dv1;
            }
        }
        if (has) {
            int nb = buf ^ 1;
            xs[nb][lt][ld] = px0;     xs[nb][lt][ld + 8] = px1;
            ds[nb][lt][ld] = pd0;     ds[nb][lt][ld + 8] = pd1;
            bs[nb][lt][ld] = pb0;     bs[nb][lt][ld + 8] = pb1;
            cs[nb][lt][ld] = pc0;     cs[nb][lt][ld + 8] = pc1;
        }
        __syncthreads();
    }
}

// ---------------- router (top-1) + bucket ----------------
__global__ void router_k(const float* __restrict__ y,
                         const float* __restrict__ Wr, const float* __restrict__ br,
                         float* __restrict__ w, int* __restrict__ eid,
                         int* __restrict__ pos, int* __restrict__ cnt) {
    int t = blockIdx.x * 4 + (threadIdx.x >> 5);
    int lane = threadIdx.x & 31;
    float a0 = 0.f, a1 = 0.f, a2 = 0.f, a3 = 0.f;
    const float* yr = y + (size_t)t * D_DIM;
    for (int k = lane; k < D_DIM; k += 32) {
        float v = yr[k];
        float4 wr = *(const float4*)&Wr[k * 4];
        a0 = fmaf(v, wr.x, a0); a1 = fmaf(v, wr.y, a1);
        a2 = fmaf(v, wr.z, a2); a3 = fmaf(v, wr.w, a3);
    }
#pragma unroll
    for (int o = 16; o; o >>= 1) {
        a0 += __shfl_xor_sync(0xffffffffu, a0, o);
        a1 += __shfl_xor_sync(0xffffffffu, a1, o);
        a2 += __shfl_xor_sync(0xffffffffu, a2, o);
        a3 += __shfl_xor_sync(0xffffffffu, a3, o);
    }
    if (lane == 0) {
        float z[4] = {a0 + br[0], a1 + br[1], a2 + br[2], a3 + br[3]};
        int best = 0; float m = z[0];
#pragma unroll
        for (int e = 1; e < 4; e++) if (z[e] > m) { m = z[e]; best = e; }
        float s = 0.f;
#pragma unroll
        for (int e = 0; e < 4; e++) s += __expf(z[e] - m);
        w[t] = 1.f / s;
        eid[t] = best;
        pos[t] = atomicAdd(&cnt[best], 1);
    }
}

__global__ void scatter_k(const int* __restrict__ eid, const int* __restrict__ pos,
                          const int* __restrict__ cnt, int* __restrict__ perm) {
    int t = blockIdx.x * 256 + threadIdx.x;
    int e = eid[t];
    int off = 0;
#pragma unroll
    for (int q = 0; q < E_EXP; q++) if (q < e) off += cnt[q];
    perm[off + pos[t]] = t;
}

// ---------------- add + split-K reduce + layernorm ----------------
__device__ __forceinline__ float block_sum(float v, float* red) {
    int lane = threadIdx.x & 31, wid = threadIdx.x >> 5;
#pragma unroll
    for (int o = 16; o; o >>= 1) v += __shfl_xor_sync(0xffffffffu, v, o);
    if (lane == 0) red[wid] = v;
    __syncthreads();
    float r = (threadIdx.x < 8) ? red[threadIdx.x] : 0.f;
    if (wid == 0) {
#pragma unroll
        for (int o = 4; o; o >>= 1) r += __shfl_xor_sync(0xffffffffu, r, o);
        if (lane == 0) red[0] = r;
    }
    __syncthreads();
    float out = red[0];
    __syncthreads();
    return out;
}

__global__ void ln_k(const float* __restrict__ y, const float* __restrict__ part,
                     const float* __restrict__ bo, const int* __restrict__ eid,
                     const float* __restrict__ wsc,
                     const float* __restrict__ g, const float* __restrict__ b,
                     float* __restrict__ h,
                     __nv_bfloat16* __restrict__ hH, __nv_bfloat16* __restrict__ hL) {
    int t = blockIdx.x, tid = threadIdx.x;
    __shared__ float red[32];
    const float* yr = y + (size_t)t * D_DIM;
    const float* pr = part + (size_t)t * D_DIM;
    const int e = eid[t];
    const float wv = wsc[t];
    const float* bo_e = bo + (size_t)e * D_DIM;
    float o[3];
    float s = 0.f;
#pragma unroll
    for (int i = 0; i < 3; i++) {
        int idx = tid + i * 256;
        float m = pr[idx];
#pragma unroll
        for (int ksl = 1; ksl < KSPL; ksl++)
            m += pr[(size_t)ksl * T_TOK * D_DIM + idx];
        m = (m + bo_e[idx]) * wv;
        o[i] = yr[idx] + m;
        s += o[i];
    }
    s = block_sum(s, red);
    float mu = s * (1.f / D_DIM);
    float sq = 0.f;
#pragma unroll
    for (int i = 0; i < 3; i++) { float d = o[i] - mu; sq += d * d; }
    sq = block_sum(sq, red);
    float inv = rsqrtf(sq * (1.f / D_DIM) + 1e-5f);
#pragma unroll
    for (int i = 0; i < 3; i++) {
        int idx = tid + i * 256;
        float val = (o[i] - mu) * inv * g[idx] + b[idx];
        size_t oi = (size_t)t * D_DIM + idx;
        h[oi] = val;
        if (hH) {
            __nv_bfloat16 hb = __float2bfloat16(val);
            hH[oi] = hb;
            hL[oi] = __float2bfloat16(val - __bfloat162float(hb));
        }
    }
}

// ---------------- launcher ----------------
extern "C" void kernel_launch(void* const* d_in, const int* in_sizes, int n_in,
                              void* d_out, int out_size) {
    (void)in_sizes; (void)n_in; (void)out_size;
    const int*   x     = (const int*)  d_in[0];
    const float* embed = (const float*)d_in[1];
    const float* A_log = (const float*)d_in[2];
    const float* Dp    = (const float*)d_in[3];
    const float* Wd    = (const float*)d_in[4];
    const float* bd    = (const float*)d_in[5];
    const float* WB    = (const float*)d_in[6];
    const float* bB    = (const float*)d_in[7];
    const float* WC    = (const float*)d_in[8];
    const float* bC    = (const float*)d_in[9];
    const float* Wr    = (const float*)d_in[10];
    const float* br    = (const float*)d_in[11];
    const float* Wu    = (const float*)d_in[12];
    const float* bu    = (const float*)d_in[13];
    const float* Wo    = (const float*)d_in[14];
    const float* bo    = (const float*)d_in[15];
    const float* lng   = (const float*)d_in[16];
    const float* lnb   = (const float*)d_in[17];
    float* out = (float*)d_out;

    float *p_h, *p_delta, *p_Bm, *p_Cm, *p_y, *p_part, *p_H, *p_w, *p_Wpack, *p_bpack;
    int *p_eid, *p_pos, *p_perm, *p_cnt;
    __nv_bfloat16 *p_eH, *p_eL, *p_hH, *p_hL;
    cudaGetSymbolAddress((void**)&p_h, g_h);
    cudaGetSymbolAddress((void**)&p_delta, g_delta);
    cudaGetSymbolAddress((void**)&p_Bm, g_Bm);
    cudaGetSymbolAddress((void**)&p_Cm, g_Cm);
    cudaGetSymbolAddress((void**)&p_y, g_y);
    cudaGetSymbolAddress((void**)&p_part, g_part);
    cudaGetSymbolAddress((void**)&p_H, g_H);
    cudaGetSymbolAddress((void**)&p_w, g_w);
    cudaGetSymbolAddress((void**)&p_Wpack, g_Wpack);
    cudaGetSymbolAddress((void**)&p_bpack, g_bpack);
    cudaGetSymbolAddress((void**)&p_eid, g_eid);
    cudaGetSymbolAddress((void**)&p_pos, g_pos);
    cudaGetSymbolAddress((void**)&p_perm, g_perm);
    cudaGetSymbolAddress((void**)&p_cnt, g_cnt);
    cudaGetSymbolAddress((void**)&p_eH, g_eH);
    cudaGetSymbolAddress((void**)&p_eL, g_eL);
    cudaGetSymbolAddress((void**)&p_hH, g_hH);
    cudaGetSymbolAddress((void**)&p_hL, g_hL);

    cudaFuncSetAttribute(logits_v2, cudaFuncAttributeMaxDynamicSharedMemorySize, LG_SMEM);

    // side stream: all 4 layer packs (needed from layer 0) then embed split (needed last)
    static cudaStream_t s2 = nullptr;
    static cudaEvent_t evFork = nullptr, evPack = nullptr, evJoin = nullptr;
    if (!s2) {
        cudaStreamCreateWithFlags(&s2, cudaStreamNonBlocking);
        cudaEventCreateWithFlags(&evFork, cudaEventDisableTiming);
        cudaEventCreateWithFlags(&evPack, cudaEventDisableTiming);
        cudaEventCreateWithFlags(&evJoin, cudaEventDisableTiming);
    }
    cudaEventRecord(evFork, 0);
    cudaStreamWaitEvent(s2, evFork, 0);
    for (int l = 0; l < NLYR; l++) {
        pack_k<<<D_DIM * NPK / 1024, 256, 0, s2>>>(
            Wd + (size_t)l * D_DIM * D_DIM,
            WB + (size_t)l * D_DIM * N_ST, WC + (size_t)l * D_DIM * N_ST,
            bd + (size_t)l * D_DIM, bB + (size_t)l * N_ST, bC + (size_t)l * N_ST,
            p_Wpack + (size_t)l * D_DIM * NPK, p_bpack + (size_t)l * NPK);
    }
    cudaEventRecord(evPack, s2);
    split_k<<<V_VOC * D_DIM / 1024, 256, 0, s2>>>(embed, p_eH, p_eL);
    cudaEventRecord(evJoin, s2);

    embed_gather_k<<<T_TOK, 192>>>(x, embed, p_h);
    cudaStreamWaitEvent(0, evPack, 0);   // all packed weights ready

    for (int l = 0; l < NLYR; l++) {
        const float* Al_l = A_log + (size_t)l * D_DIM * N_ST;
        const float* Dp_l = Dp + (size_t)l * D_DIM;
        const float* Wr_l = Wr + (size_t)l * D_DIM * E_EXP;
        const float* br_l = br + (size_t)l * E_EXP;
        const float* Wu_l = Wu + (size_t)l * E_EXP * D_DIM * DFF_F;
        const float* bu_l = bu + (size_t)l * E_EXP * DFF_F;
        const float* Wo_l = Wo + (size_t)l * E_EXP * DFF_F * D_DIM;
        const float* bo_l = bo + (size_t)l * E_EXP * D_DIM;
        const float* g_l  = lng + (size_t)l * D_DIM;
        const float* b_l  = lnb + (size_t)l * D_DIM;

        gemm_tc<4, 1><<<dim3(NPK / 64, T_TOK / 128), 256>>>(
            p_h, p_Wpack + (size_t)l * D_DIM * NPK, p_bpack + (size_t)l * NPK,
            p_delta, NPK, D_DIM, nullptr, nullptr, nullptr, p_Bm, p_Cm);
        // scan (2 chains/thread) + zero cnt for router
        scan_k<<<dim3(D_DIM / 16, BSZ), 128>>>(p_h, p_delta, p_Bm, p_Cm, Al_l, Dp_l,
                                               p_y, p_cnt);
        router_k<<<T_TOK / 4, 128>>>(p_y, Wr_l, br_l, p_w, p_eid, p_pos, p_cnt);
        scatter_k<<<T_TOK / 256, 256>>>(p_eid, p_pos, p_cnt, p_perm);
        gemm_tc<2, 2><<<dim3(DFF_F / 64, T_TOK / 128, E_EXP), 256>>>(
            p_y, Wu_l, bu_l, p_H, DFF_F, D_DIM,
            p_perm, nullptr, p_cnt, nullptr, nullptr);
        gemm_tc<5, 0><<<dim3(D_DIM / 64, T_TOK / 128, E_EXP * KSPL), 256>>>(
            p_H, Wo_l, nullptr, p_part, D_DIM, DFF_F / KSPL,
            p_perm, nullptr, p_cnt, nullptr, nullptr);
        ln_k<<<T_TOK, 256>>>(p_y, p_part, bo_l, p_eid, p_w, g_l, b_l, p_h,
                             (l == NLYR - 1) ? p_hH : nullptr,
                             (l == NLYR - 1) ? p_hL : nullptr);
    }

    cudaStreamWaitEvent(0, evJoin, 0);
    logits_v2<<<dim3(T_TOK / 128, V_VOC / 128), 256, LG_SMEM>>>(p_hH, p_hL, p_eH, p_eL, out);
}

// round 14
// speedup vs baseline: 1.0611x; 1.0611x over previous
#include <cuda_runtime.h>
#include <cuda_bf16.h>
#include <math.h>
#include <stdint.h>

#define T_TOK 4096
#define D_DIM 768
#define N_ST  16
#define E_EXP 4
#define DFF_F 3072
#define V_VOC 32000
#define NLYR  4
#define BSZ   2
#define SEQL  2048
#define NPK   832      // packed delta|B|C width: 768 + 16 + 16 + 32 pad
#define KSPL  4        // split-K factor for MoE down

// ---------------- scratch ----------------
__device__ float g_h[T_TOK * D_DIM];
__device__ float g_delta[T_TOK * D_DIM];
__device__ float g_Bm[T_TOK * N_ST];
__device__ float g_Cm[T_TOK * N_ST];
__device__ float g_y[T_TOK * D_DIM];
__device__ float g_part[KSPL * T_TOK * D_DIM];
__device__ float g_H[T_TOK * DFF_F];
__device__ float g_w[T_TOK];
__device__ int   g_eid[T_TOK];
__device__ int   g_pos[T_TOK];
__device__ int   g_perm[T_TOK];
__device__ int   g_cnt[E_EXP];
__device__ float g_Wpack[NLYR * D_DIM * NPK];
__device__ float g_bpack[NLYR * NPK];
__device__ __nv_bfloat16 g_eH[V_VOC * D_DIM];
__device__ __nv_bfloat16 g_eL[V_VOC * D_DIM];
__device__ __nv_bfloat16 g_hH[T_TOK * D_DIM];
__device__ __nv_bfloat16 g_hL[T_TOK * D_DIM];

// ---------------- helpers ----------------
__device__ __forceinline__ uint32_t smem_u32(const void* p) {
    uint32_t a;
    asm("{ .reg .u64 t; cvta.to.shared.u64 t, %1; cvt.u32.u64 %0, t; }" : "=r"(a) : "l"(p));
    return a;
}
__device__ __forceinline__ void cp16(uint32_t s, const void* g) {
    asm volatile("cp.async.cg.shared.global [%0], [%1], 16;" :: "r"(s), "l"(g));
}
#define CP_COMMIT() asm volatile("cp.async.commit_group;" ::: "memory")
#define CP_WAIT1()  asm volatile("cp.async.wait_group 1;" ::: "memory")
#define CP_WAIT0()  asm volatile("cp.async.wait_group 0;" ::: "memory")

#define LDSM4(R0,R1,R2,R3,ADDR) \
    asm volatile("ldmatrix.sync.aligned.m8n8.x4.shared.b16 {%0,%1,%2,%3}, [%4];" \
        : "=r"(R0),"=r"(R1),"=r"(R2),"=r"(R3) : "r"(ADDR))
#define LDSM4T(R0,R1,R2,R3,ADDR) \
    asm volatile("ldmatrix.sync.aligned.m8n8.x4.trans.shared.b16 {%0,%1,%2,%3}, [%4];" \
        : "=r"(R0),"=r"(R1),"=r"(R2),"=r"(R3) : "r"(ADDR))
#define MMA_BF16(D,AV,BV) \
    asm volatile("mma.sync.aligned.m16n8k16.row.col.f32.bf16.bf16.f32 " \
        "{%0,%1,%2,%3}, {%4,%5,%6,%7}, {%8,%9}, {%0,%1,%2,%3};" \
        : "+f"((D)[0]),"+f"((D)[1]),"+f"((D)[2]),"+f"((D)[3]) \
        : "r"((AV)[0]),"r"((AV)[1]),"r"((AV)[2]),"r"((AV)[3]), \
          "r"((BV)[0]),"r"((BV)[1]))

__device__ __forceinline__ void splt(float v, uint32_t& h, uint32_t& l) {
    __nv_bfloat16 bh = __float2bfloat16(v);
    float r = v - __bfloat162float(bh);
    __nv_bfloat16 bl = __float2bfloat16(r);
    h = (uint32_t)__bfloat16_as_ushort(bh);
    l = (uint32_t)__bfloat16_as_ushort(bl);
}
__device__ __forceinline__ void split_pack(float a, float b, uint32_t& hp, uint32_t& lp) {
    uint32_t h0, l0, h1, l1;
    splt(a, h0, l0); splt(b, h1, l1);
    hp = h0 | (h1 << 16);
    lp = l0 | (l1 << 16);
}

// ---------------- embed gather ----------------
__global__ void embed_gather_k(const int* __restrict__ x,
                               const float* __restrict__ embed,
                               float* __restrict__ h) {
    int t = blockIdx.x;
    int tok = x[t];
    const float4* src = (const float4*)(embed + (size_t)tok * D_DIM);
    float4* dst = (float4*)(h + (size_t)t * D_DIM);
    dst[threadIdx.x] = src[threadIdx.x];
}

// ---------------- fp32 -> split-bf16 planes ----------------
__global__ void split_k(const float* __restrict__ s,
                        __nv_bfloat16* __restrict__ hi,
                        __nv_bfloat16* __restrict__ lo) {
    size_t i = ((size_t)blockIdx.x * 256 + threadIdx.x) * 4;
    float4 v = *(const float4*)(s + i);
    uint32_t hp0, lp0, hp1, lp1;
    split_pack(v.x, v.y, hp0, lp0);
    split_pack(v.z, v.w, hp1, lp1);
    *(uint2*)(hi + i) = make_uint2(hp0, hp1);
    *(uint2*)(lo + i) = make_uint2(lp0, lp1);
}

// ---------------- pack [Wd|WB|WC] -> [768, 832] fp32 + biases ----------------
__global__ void pack_k(const float* __restrict__ Wd, const float* __restrict__ WB,
                       const float* __restrict__ WC,
                       const float* __restrict__ bd, const float* __restrict__ bB,
                       const float* __restrict__ bC,
                       float* __restrict__ Wp, float* __restrict__ bp) {
    int i = (blockIdx.x * 256 + threadIdx.x) * 4;
    int k = i / NPK, c = i % NPK;
#pragma unroll
    for (int j = 0; j < 4; j++) {
        int c2 = c + j;
        float v;
        if (c2 < 768)      v = Wd[k * D_DIM + c2];
        else if (c2 < 784) v = WB[k * N_ST + c2 - 768];
        else if (c2 < 800) v = WC[k * N_ST + c2 - 784];
        else               v = 0.f;
        Wp[i + j] = v;
    }
    if (blockIdx.x == 0) {
        for (int c2 = threadIdx.x; c2 < NPK; c2 += 256) {
            float v;
            if (c2 < 768)      v = bd[c2];
            else if (c2 < 784) v = bB[c2 - 768];
            else if (c2 < 800) v = bC[c2 - 784];
            else               v = 0.f;
            bp[c2] = v;
        }
    }
}

#define PA 40   // A smem pitch in bf16
#define PB 72   // B smem pitch (k-major) in bf16

// ---------------- logits GEMM v2 (proven) ----------------
#define LG_SMEM 81920

__global__ void __launch_bounds__(256, 2) logits_v2(
    const __nv_bfloat16* __restrict__ hH, const __nv_bfloat16* __restrict__ hL,
    const __nv_bfloat16* __restrict__ eH, const __nv_bfloat16* __restrict__ eL,
    float* __restrict__ out)
{
    extern __shared__ char dsm[];
    const uint32_t sb = smem_u32(dsm);
    const int tid = threadIdx.x;
    const int bm = blockIdx.x * 128;
    const int bn = blockIdx.y * 128;

    const int w = tid >> 5, lane = tid & 31;
    const int wm = (w >> 1) * 32, wn = (w & 1) * 64;

    const int lrow = tid >> 1;
    const int lsegB = (tid & 1) * 32;
    const int lsegE = (tid & 1) * 16;
    const uint32_t sRow = (uint32_t)(lrow * 80 + lsegB);

#define LG_ISSUE(C) do {                                                        \
    const int k0_ = (C) * 32;                                                   \
    const uint32_t s0_ = sb + ((C) & 1) * 40960;                                \
    const __nv_bfloat16* g_;                                                    \
    g_ = hH + (size_t)(bm + lrow) * D_DIM + k0_ + lsegE;                        \
    cp16(s0_ + sRow, g_); cp16(s0_ + sRow + 16, g_ + 8);                        \
    g_ = hL + (size_t)(bm + lrow) * D_DIM + k0_ + lsegE;                        \
    cp16(s0_ + 10240 + sRow, g_); cp16(s0_ + 10240 + sRow + 16, g_ + 8);        \
    g_ = eH + (size_t)(bn + lrow) * D_DIM + k0_ + lsegE;                        \
    cp16(s0_ + 20480 + sRow, g_); cp16(s0_ + 20480 + sRow + 16, g_ + 8);        \
    g_ = eL + (size_t)(bn + lrow) * D_DIM + k0_ + lsegE;                        \
    cp16(s0_ + 30720 + sRow, g_); cp16(s0_ + 30720 + sRow + 16, g_ + 8);        \
    CP_COMMIT(); } while (0)

    const uint32_t a_off = (uint32_t)((lane & 15) * (PA * 2) + ((lane >> 4) & 1) * 16);
    uint32_t aB[2];
#pragma unroll
    for (int mi = 0; mi < 2; mi++) aB[mi] = (uint32_t)((wm + mi * 16) * (PA * 2)) + a_off;

    const uint32_t b_off = (uint32_t)(((lane & 7) + ((lane >> 4) & 1) * 8) * (PA * 2)
                                      + ((lane >> 3) & 1) * 16);
    uint32_t bB[4];
#pragma unroll
    for (int j = 0; j < 4; j++) bB[j] = (uint32_t)((wn + j * 16) * (PA * 2)) + b_off;

    float acc[2][8][4];
#pragma unroll
    for (int mi = 0; mi < 2; mi++)
#pragma unroll
        for (int nj = 0; nj < 8; nj++)
#pragma unroll
            for (int q = 0; q < 4; q++) acc[mi][nj][q] = 0.f;

    LG_ISSUE(0);
    LG_ISSUE(1);

    const int NC = D_DIM / 32;
    for (int c = 0; c < NC; c++) {
        if (c + 1 < NC) { CP_WAIT1(); } else { CP_WAIT0(); }
        __syncthreads();
        const uint32_t base = sb + (c & 1) * 40960;
#pragma unroll
        for (int kk = 0; kk < 32; kk += 16) {
            uint32_t ah[2][4], al[2][4], bh[8][2], bl[8][2];
#pragma unroll
            for (int mi = 0; mi < 2; mi++) {
                LDSM4(ah[mi][0], ah[mi][1], ah[mi][2], ah[mi][3], base + aB[mi] + kk * 2);
                LDSM4(al[mi][0], al[mi][1], al[mi][2], al[mi][3],
                      base + 10240 + aB[mi] + kk * 2);
            }
#pragma unroll
            for (int j = 0; j < 4; j++) {
                uint32_t r0, r1, r2, r3;
                LDSM4(r0, r1, r2, r3, base + 20480 + bB[j] + kk * 2);
                bh[2 * j][0] = r0; bh[2 * j][1] = r1;
                bh[2 * j + 1][0] = r2; bh[2 * j + 1][1] = r3;
                LDSM4(r0, r1, r2, r3, base + 30720 + bB[j] + kk * 2);
                bl[2 * j][0] = r0; bl[2 * j][1] = r1;
                bl[2 * j + 1][0] = r2; bl[2 * j + 1][1] = r3;
            }
#pragma unroll
            for (int mi = 0; mi < 2; mi++)
#pragma unroll
                for (int nj = 0; nj < 8; nj++) {
                    MMA_BF16(acc[mi][nj], ah[mi], bh[nj]);
                    MMA_BF16(acc[mi][nj], ah[mi], bl[nj]);
                    MMA_BF16(acc[mi][nj], al[mi], bh[nj]);
                }
        }
        __syncthreads();
        if (c + 2 < NC) LG_ISSUE(c + 2);
    }

#pragma unroll
    for (int mi = 0; mi < 2; mi++) {
#pragma unroll
        for (int half = 0; half < 2; half++) {
            int row = bm + wm + mi * 16 + (lane >> 2) + half * 8;
            float* orow = out + (size_t)row * V_VOC + bn + wn;
#pragma unroll
            for (int nj = 0; nj < 8; nj++) {
                int col = nj * 8 + (lane & 3) * 2;
                *(float2*)(orow + col) =
                    make_float2(acc[mi][nj][half * 2], acc[mi][nj][half * 2 + 1]);
            }
        }
    }
}

// ---------------- mma.sync GEMM (in-loop split-bf16 convert) ----------------
// MODE 2: MoE up gather rows (bias+silu)
// MODE 4: fused delta|B|C: dense A, packed B (N=832), region epilogue
// MODE 5: MoE down split-K: z = e*KSPL+ks; partial out, no bias/act
template<int MODE, int ACT>
__global__ void __launch_bounds__(256) gemm_tc(
    const float* __restrict__ A, const float* __restrict__ B,
    const float* __restrict__ bias, float* __restrict__ C,
    int N, int K,
    const int* __restrict__ perm, const float* __restrict__ wsc,
    const int* __restrict__ cnt,
    float* __restrict__ BmOut, float* __restrict__ CmOut)
{
    __shared__ __align__(16) __nv_bfloat16 Ah[128 * PA], Al[128 * PA];
    __shared__ __align__(16) __nv_bfloat16 Bh[2560], Bl[2560];

    const int tid = threadIdx.x;
    const int bn = blockIdx.x * 64;
    const int bm = blockIdx.y * 128;

    int cnt_e = 0, off_e = 0, ks = 0;
    if (MODE == 2 || MODE == 5) {
        int e = (MODE == 5) ? (blockIdx.z >> 2) : blockIdx.z;
        if (MODE == 5) ks = blockIdx.z & 3;
        cnt_e = cnt[e];
        for (int q = 0; q < E_EXP; q++) if (q < e) off_e += cnt[q];
        if (bm >= cnt_e) return;
        if (MODE == 2) {
            B += (size_t)e * K * N;
            bias += (size_t)e * N;
        } else {
            B += ((size_t)e * DFF_F + (size_t)ks * (DFF_F / KSPL)) * N;
        }
    }

    const int ar = tid >> 3;
    const int ac = (tid & 7) * 4;
    const float* arow[4];
#pragma unroll
    for (int i = 0; i < 4; i++) {
        int g = bm + ar + 32 * i;
        if (MODE == 4) arow[i] = A + (size_t)g * K;
        else if (MODE == 2) arow[i] = (g < cnt_e) ? A + (size_t)perm[off_e + g] * K : nullptr;
        else arow[i] = (g < cnt_e)
            ? A + (size_t)(off_e + g) * DFF_F + (size_t)ks * (DFF_F / KSPL) : nullptr;
    }
    const int bkr = tid >> 4;
    const int bbc = (tid & 15) * 4;

    const int w = tid >> 5, lane = tid & 31;
    const int wm = (w >> 1) * 32, wn = (w & 1) * 32;
    const uint32_t sAh = (uint32_t)__cvta_generic_to_shared(Ah);
    const uint32_t sAl = (uint32_t)__cvta_generic_to_shared(Al);
    const uint32_t sBh = (uint32_t)__cvta_generic_to_shared(Bh);
    const uint32_t sBl = (uint32_t)__cvta_generic_to_shared(Bl);

    const uint32_t a_off = (uint32_t)((lane & 15) * (PA * 2) + ((lane >> 4) & 1) * 16);
    uint32_t aBase[2];
#pragma unroll
    for (int mi = 0; mi < 2; mi++)
        aBase[mi] = (uint32_t)((wm + mi * 16) * (PA * 2)) + a_off;

    uint32_t bBase[2];
    {
        uint32_t b_off = (uint32_t)((lane & 15) * (PB * 2) + ((lane >> 4) & 1) * 16);
#pragma unroll
        for (int ni2 = 0; ni2 < 2; ni2++)
            bBase[ni2] = (uint32_t)((wn + ni2 * 16) * 2) + b_off;
    }

    float acc[2][4][4];
#pragma unroll
    for (int mi = 0; mi < 2; mi++)
#pragma unroll
        for (int nj = 0; nj < 4; nj++)
#pragma unroll
            for (int q = 0; q < 4; q++) acc[mi][nj][q] = 0.f;

    float4 av[4], bv[2];

#define LOAD_G(K0) do {                                                          \
    _Pragma("unroll")                                                            \
    for (int i = 0; i < 4; i++)                                                  \
        av[i] = arow[i] ? *(const float4*)(arow[i] + (K0) + ac)                  \
                        : make_float4(0.f, 0.f, 0.f, 0.f);                       \
    _Pragma("unroll")                                                            \
    for (int i = 0; i < 2; i++)                                                  \
        bv[i] = *(const float4*)(B + (size_t)((K0) + bkr + 16 * i) * N + bn + bbc); \
    } while (0)

#define STORE_S() do {                                                           \
    _Pragma("unroll")                                                            \
    for (int i = 0; i < 4; i++) {                                                \
        int row = ar + 32 * i;                                                   \
        uint32_t h0, l0, h1, l1;                                                 \
        split_pack(av[i].x, av[i].y, h0, l0);                                    \
        split_pack(av[i].z, av[i].w, h1, l1);                                    \
        uint32_t* pH = (uint32_t*)(Ah + row * PA + ac);                          \
        uint32_t* pL = (uint32_t*)(Al + row * PA + ac);                          \
        pH[0] = h0; pH[1] = h1; pL[0] = l0; pL[1] = l1;                          \
    }                                                                            \
    _Pragma("unroll")                                                            \
    for (int i = 0; i < 2; i++) {                                                \
        uint32_t h0, l0, h1, l1;                                                 \
        split_pack(bv[i].x, bv[i].y, h0, l0);                                    \
        split_pack(bv[i].z, bv[i].w, h1, l1);                                    \
        uint32_t* pH = (uint32_t*)(Bh + (bkr + 16 * i) * PB + bbc);              \
        uint32_t* pL = (uint32_t*)(Bl + (bkr + 16 * i) * PB + bbc);              \
        pH[0] = h0; pH[1] = h1; pL[0] = l0; pL[1] = l1;                          \
    } } while (0)

    LOAD_G(0);
    for (int k0 = 0; k0 < K; k0 += 32) {
        STORE_S();
        __syncthreads();
        if (k0 + 32 < K) LOAD_G(k0 + 32);

#pragma unroll
        for (int kk = 0; kk < 32; kk += 16) {
            uint32_t ah[2][4], alr[2][4], bhf[4][2], blf[4][2];
#pragma unroll
            for (int mi = 0; mi < 2; mi++) {
                LDSM4(ah[mi][0], ah[mi][1], ah[mi][2], ah[mi][3], sAh + aBase[mi] + kk * 2);
                LDSM4(alr[mi][0], alr[mi][1], alr[mi][2], alr[mi][3], sAl + aBase[mi] + kk * 2);
            }
#pragma unroll
            for (int ni2 = 0; ni2 < 2; ni2++) {
                uint32_t r0, r1, r2, r3;
                LDSM4T(r0, r1, r2, r3, sBh + bBase[ni2] + kk * (PB * 2));
                bhf[2 * ni2][0] = r0; bhf[2 * ni2][1] = r1;
                bhf[2 * ni2 + 1][0] = r2; bhf[2 * ni2 + 1][1] = r3;
                LDSM4T(r0, r1, r2, r3, sBl + bBase[ni2] + kk * (PB * 2));
                blf[2 * ni2][0] = r0; blf[2 * ni2][1] = r1;
                blf[2 * ni2 + 1][0] = r2; blf[2 * ni2 + 1][1] = r3;
            }
#pragma unroll
            for (int mi = 0; mi < 2; mi++)
#pragma unroll
                for (int nj = 0; nj < 4; nj++) {
                    MMA_BF16(acc[mi][nj], ah[mi], bhf[nj]);
                    MMA_BF16(acc[mi][nj], ah[mi], blf[nj]);
                    MMA_BF16(acc[mi][nj], alr[mi], bhf[nj]);
                }
        }
        __syncthreads();
    }

#pragma unroll
    for (int mi = 0; mi < 2; mi++) {
#pragma unroll
        for (int half = 0; half < 2; half++) {
            int tr = wm + mi * 16 + (lane >> 2) + half * 8;
            int g = bm + tr;
            size_t orow = (size_t)g;
            bool valid = true;
            if (MODE == 2) { valid = g < cnt_e; orow = (size_t)(off_e + g); }
            else if (MODE == 5) {
                valid = g < cnt_e;
                int tok = valid ? perm[off_e + g] : 0;
                orow = (size_t)ks * T_TOK + tok;
            }
            if (!valid) continue;
#pragma unroll
            for (int nj = 0; nj < 4; nj++) {
                int col = bn + wn + nj * 8 + (lane & 3) * 2;
                float u0 = acc[mi][nj][half * 2 + 0];
                float u1 = acc[mi][nj][half * 2 + 1];
                if (MODE == 5) {
                    *(float2*)(C + orow * (size_t)N + col) = make_float2(u0, u1);
                    continue;
                }
                float2 bb = *(const float2*)&bias[col];
                u0 += bb.x; u1 += bb.y;
                if (MODE == 4) {
                    if (col < 768) {
                        u0 = fmaxf(u0, 0.f) + log1pf(expf(-fabsf(u0)));
                        u1 = fmaxf(u1, 0.f) + log1pf(expf(-fabsf(u1)));
                        *(float2*)(C + orow * (size_t)D_DIM + col) = make_float2(u0, u1);
                    } else if (col < 784) {
                        *(float2*)(BmOut + orow * (size_t)N_ST + col - 768) = make_float2(u0, u1);
                    } else if (col < 800) {
                        *(float2*)(CmOut + orow * (size_t)N_ST + col - 784) = make_float2(u0, u1);
                    }
                    continue;
                }
                if (ACT == 2) {
                    u0 = u0 / (1.f + __expf(-u0));
                    u1 = u1 / (1.f + __expf(-u1));
                }
                *(float2*)(C + orow * (size_t)N + col) = make_float2(u0, u1);
            }
        }
    }
}

// ---------------- SSM sequential scan (R12-proven: 8 d per block, 192 blocks) ----
__global__ void __launch_bounds__(128) scan_k(
    const float* __restrict__ h, const float* __restrict__ delta,
    const float* __restrict__ Bm, const float* __restrict__ Cm,
    const float* __restrict__ A_log, const float* __restrict__ Dp,
    float* __restrict__ y, int* __restrict__ cnt)
{
    const int b  = blockIdx.y;
    const int d0 = blockIdx.x * 8;
    const int tid = threadIdx.x;
    const int dg = tid >> 4;
    const int n  = tid & 15;
    const int d  = d0 + dg;

    if (blockIdx.x == 0 && b == 0 && tid < E_EXP) cnt[tid] = 0;

    const float a  = -expf(A_log[d * N_ST + n]);
    const float Dv = Dp[d];
    float hs = 0.f;

    __shared__ float xs[2][16][8], ds[2][16][8];
    __shared__ float bs[2][16][16], cs[2][16][16];

    const int lt = tid >> 3;
    const int ld = tid & 7;
    const size_t tok0 = (size_t)b * SEQL;

    xs[0][lt][ld] = h[(tok0 + lt) * D_DIM + d0 + ld];
    ds[0][lt][ld] = delta[(tok0 + lt) * D_DIM + d0 + ld];
    bs[0][lt][ld]     = Bm[(tok0 + lt) * N_ST + ld];
    bs[0][lt][ld + 8] = Bm[(tok0 + lt) * N_ST + ld + 8];
    cs[0][lt][ld]     = Cm[(tok0 + lt) * N_ST + ld];
    cs[0][lt][ld + 8] = Cm[(tok0 + lt) * N_ST + ld + 8];
    __syncthreads();

    const int NCH = SEQL / 16;
    for (int c = 0; c < NCH; c++) {
        int buf = c & 1;
        float px = 0.f, pd = 0.f, pb0 = 0.f, pb1 = 0.f, pc0 = 0.f, pc1 = 0.f;
        bool has = (c + 1) < NCH;
        if (has) {
            size_t t1 = tok0 + (c + 1) * 16 + lt;
            px = h[t1 * D_DIM + d0 + ld];
            pd = delta[t1 * D_DIM + d0 + ld];
            pb0 = Bm[t1 * N_ST + ld];  pb1 = Bm[t1 * N_ST + ld + 8];
            pc0 = Cm[t1 * N_ST + ld];  pc1 = Cm[t1 * N_ST + ld + 8];
        }
        int tbase = c * 16;
#pragma unroll
        for (int s = 0; s < 16; s++) {
            float xv = xs[buf][s][dg];
            float dv = ds[buf][s][dg];
            float Bv = bs[buf][s][n];
            float Cv = cs[buf][s][n];
            float barA = __expf(fminf(dv * a, 2.f));
            float barB = fminf(fmaxf(dv * Bv, -2.f), 2.f);
            hs = fminf(fmaxf(fmaf(barA, hs, barB * xv), -100.f), 100.f);
            float p = hs * Cv;
            p += __shfl_xor_sync(0xffffffffu, p, 1, 16);
            p += __shfl_xor_sync(0xffffffffu, p, 2, 16);
            p += __shfl_xor_sync(0xffffffffu, p, 4, 16);
            p += __shfl_xor_sync(0xffffffffu, p, 8, 16);
            if (n == 0)
                y[(tok0 + tbase + s) * D_DIM + d] = p + xv * Dv;
        }
        if (has) {
            int nb = buf ^ 1;
            xs[nb][lt][ld] = px;
            ds[nb][lt][ld] = pd;
            bs[nb][lt][ld] = pb0; bs[nb][lt][ld + 8] = pb1;
            cs[nb][lt][ld] = pc0; cs[nb][lt][ld + 8] = pc1;
        }
        __syncthreads();
    }
}

// ---------------- router (top-1) + bucket ----------------
__global__ void router_k(const float* __restrict__ y,
                         const float* __restrict__ Wr, const float* __restrict__ br,
                         float* __restrict__ w, int* __restrict__ eid,
                         int* __restrict__ pos, int* __restrict__ cnt) {
    int t = blockIdx.x * 4 + (threadIdx.x >> 5);
    int lane = threadIdx.x & 31;
    float a0 = 0.f, a1 = 0.f, a2 = 0.f, a3 = 0.f;
    const float* yr = y + (size_t)t * D_DIM;
    for (int k = lane; k < D_DIM; k += 32) {
        float v = yr[k];
        float4 wr = *(const float4*)&Wr[k * 4];
        a0 = fmaf(v, wr.x, a0); a1 = fmaf(v, wr.y, a1);
        a2 = fmaf(v, wr.z, a2); a3 = fmaf(v, wr.w, a3);
    }
#pragma unroll
    for (int o = 16; o; o >>= 1) {
        a0 += __shfl_xor_sync(0xffffffffu, a0, o);
        a1 += __shfl_xor_sync(0xffffffffu, a1, o);
        a2 += __shfl_xor_sync(0xffffffffu, a2, o);
        a3 += __shfl_xor_sync(0xffffffffu, a3, o);
    }
    if (lane == 0) {
        float z[4] = {a0 + br[0], a1 + br[1], a2 + br[2], a3 + br[3]};
        int best = 0; float m = z[0];
#pragma unroll
        for (int e = 1; e < 4; e++) if (z[e] > m) { m = z[e]; best = e; }
        float s = 0.f;
#pragma unroll
        for (int e = 0; e < 4; e++) s += __expf(z[e] - m);
        w[t] = 1.f / s;
        eid[t] = best;
        pos[t] = atomicAdd(&cnt[best], 1);
    }
}

__global__ void scatter_k(const int* __restrict__ eid, const int* __restrict__ pos,
                          const int* __restrict__ cnt, int* __restrict__ perm) {
    int t = blockIdx.x * 256 + threadIdx.x;
    int e = eid[t];
    int off = 0;
#pragma unroll
    for (int q = 0; q < E_EXP; q++) if (q < e) off += cnt[q];
    perm[off + pos[t]] = t;
}

// ---------------- add + split-K reduce + layernorm ----------------
__device__ __forceinline__ float block_sum(float v, float* red) {
    int lane = threadIdx.x & 31, wid = threadIdx.x >> 5;
#pragma unroll
    for (int o = 16; o; o >>= 1) v += __shfl_xor_sync(0xffffffffu, v, o);
    if (lane == 0) red[wid] = v;
    __syncthreads();
    float r = (threadIdx.x < 8) ? red[threadIdx.x] : 0.f;
    if (wid == 0) {
#pragma unroll
        for (int o = 4; o; o >>= 1) r += __shfl_xor_sync(0xffffffffu, r, o);
        if (lane == 0) red[0] = r;
    }
    __syncthreads();
    float out = red[0];
    __syncthreads();
    return out;
}

__global__ void ln_k(const float* __restrict__ y, const float* __restrict__ part,
                     const float* __restrict__ bo, const int* __restrict__ eid,
                     const float* __restrict__ wsc,
                     const float* __restrict__ g, const float* __restrict__ b,
                     float* __restrict__ h,
                     __nv_bfloat16* __restrict__ hH, __nv_bfloat16* __restrict__ hL) {
    int t = blockIdx.x, tid = threadIdx.x;
    __shared__ float red[32];
    const float* yr = y + (size_t)t * D_DIM;
    const float* pr = part + (size_t)t * D_DIM;
    const int e = eid[t];
    const float wv = wsc[t];
    const float* bo_e = bo + (size_t)e * D_DIM;
    float o[3];
    float s = 0.f;
#pragma unroll
    for (int i = 0; i < 3; i++) {
        int idx = tid + i * 256;
        float m = pr[idx];
#pragma unroll
        for (int ksl = 1; ksl < KSPL; ksl++)
            m += pr[(size_t)ksl * T_TOK * D_DIM + idx];
        m = (m + bo_e[idx]) * wv;
        o[i] = yr[idx] + m;
        s += o[i];
    }
    s = block_sum(s, red);
    float mu = s * (1.f / D_DIM);
    float sq = 0.f;
#pragma unroll
    for (int i = 0; i < 3; i++) { float d = o[i] - mu; sq += d * d; }
    sq = block_sum(sq, red);
    float inv = rsqrtf(sq * (1.f / D_DIM) + 1e-5f);
#pragma unroll
    for (int i = 0; i < 3; i++) {
        int idx = tid + i * 256;
        float val = (o[i] - mu) * inv * g[idx] + b[idx];
        size_t oi = (size_t)t * D_DIM + idx;
        h[oi] = val;
        if (hH) {
            __nv_bfloat16 hb = __float2bfloat16(val);
            hH[oi] = hb;
            hL[oi] = __float2bfloat16(val - __bfloat162float(hb));
        }
    }
}

// ---------------- launcher ----------------
extern "C" void kernel_launch(void* const* d_in, const int* in_sizes, int n_in,
                              void* d_out, int out_size) {
    (void)in_sizes; (void)n_in; (void)out_size;
    const int*   x     = (const int*)  d_in[0];
    const float* embed = (const float*)d_in[1];
    const float* A_log = (const float*)d_in[2];
    const float* Dp    = (const float*)d_in[3];
    const float* Wd    = (const float*)d_in[4];
    const float* bd    = (const float*)d_in[5];
    const float* WB    = (const float*)d_in[6];
    const float* bB    = (const float*)d_in[7];
    const float* WC    = (const float*)d_in[8];
    const float* bC    = (const float*)d_in[9];
    const float* Wr    = (const float*)d_in[10];
    const float* br    = (const float*)d_in[11];
    const float* Wu    = (const float*)d_in[12];
    const float* bu    = (const float*)d_in[13];
    const float* Wo    = (const float*)d_in[14];
    const float* bo    = (const float*)d_in[15];
    const float* lng   = (const float*)d_in[16];
    const float* lnb   = (const float*)d_in[17];
    float* out = (float*)d_out;

    float *p_h, *p_delta, *p_Bm, *p_Cm, *p_y, *p_part, *p_H, *p_w, *p_Wpack, *p_bpack;
    int *p_eid, *p_pos, *p_perm, *p_cnt;
    __nv_bfloat16 *p_eH, *p_eL, *p_hH, *p_hL;
    cudaGetSymbolAddress((void**)&p_h, g_h);
    cudaGetSymbolAddress((void**)&p_delta, g_delta);
    cudaGetSymbolAddress((void**)&p_Bm, g_Bm);
    cudaGetSymbolAddress((void**)&p_Cm, g_Cm);
    cudaGetSymbolAddress((void**)&p_y, g_y);
    cudaGetSymbolAddress((void**)&p_part, g_part);
    cudaGetSymbolAddress((void**)&p_H, g_H);
    cudaGetSymbolAddress((void**)&p_w, g_w);
    cudaGetSymbolAddress((void**)&p_Wpack, g_Wpack);
    cudaGetSymbolAddress((void**)&p_bpack, g_bpack);
    cudaGetSymbolAddress((void**)&p_eid, g_eid);
    cudaGetSymbolAddress((void**)&p_pos, g_pos);
    cudaGetSymbolAddress((void**)&p_perm, g_perm);
    cudaGetSymbolAddress((void**)&p_cnt, g_cnt);
    cudaGetSymbolAddress((void**)&p_eH, g_eH);
    cudaGetSymbolAddress((void**)&p_eL, g_eL);
    cudaGetSymbolAddress((void**)&p_hH, g_hH);
    cudaGetSymbolAddress((void**)&p_hL, g_hL);

    cudaFuncSetAttribute(logits_v2, cudaFuncAttributeMaxDynamicSharedMemorySize, LG_SMEM);

    // side stream: all 4 layer packs (needed from layer 0) then embed split (needed last)
    static cudaStream_t s2 = nullptr;
    static cudaEvent_t evFork = nullptr, evPack = nullptr, evJoin = nullptr;
    if (!s2) {
        cudaStreamCreateWithFlags(&s2, cudaStreamNonBlocking);
        cudaEventCreateWithFlags(&evFork, cudaEventDisableTiming);
        cudaEventCreateWithFlags(&evPack, cudaEventDisableTiming);
        cudaEventCreateWithFlags(&evJoin, cudaEventDisableTiming);
    }
    cudaEventRecord(evFork, 0);
    cudaStreamWaitEvent(s2, evFork, 0);
    for (int l = 0; l < NLYR; l++) {
        pack_k<<<D_DIM * NPK / 1024, 256, 0, s2>>>(
            Wd + (size_t)l * D_DIM * D_DIM,
            WB + (size_t)l * D_DIM * N_ST, WC + (size_t)l * D_DIM * N_ST,
            bd + (size_t)l * D_DIM, bB + (size_t)l * N_ST, bC + (size_t)l * N_ST,
            p_Wpack + (size_t)l * D_DIM * NPK, p_bpack + (size_t)l * NPK);
    }
    cudaEventRecord(evPack, s2);
    split_k<<<V_VOC * D_DIM / 1024, 256, 0, s2>>>(embed, p_eH, p_eL);
    cudaEventRecord(evJoin, s2);

    embed_gather_k<<<T_TOK, 192>>>(x, embed, p_h);
    cudaStreamWaitEvent(0, evPack, 0);   // all packed weights ready

    for (int l = 0; l < NLYR; l++) {
        const float* Al_l = A_log + (size_t)l * D_DIM * N_ST;
        const float* Dp_l = Dp + (size_t)l * D_DIM;
        const float* Wr_l = Wr + (size_t)l * D_DIM * E_EXP;
        const float* br_l = br + (size_t)l * E_EXP;
        const float* Wu_l = Wu + (size_t)l * E_EXP * D_DIM * DFF_F;
        const float* bu_l = bu + (size_t)l * E_EXP * DFF_F;
        const float* Wo_l = Wo + (size_t)l * E_EXP * DFF_F * D_DIM;
        const float* bo_l = bo + (size_t)l * E_EXP * D_DIM;
        const float* g_l  = lng + (size_t)l * D_DIM;
        const float* b_l  = lnb + (size_t)l * D_DIM;

        gemm_tc<4, 1><<<dim3(NPK / 64, T_TOK / 128), 256>>>(
            p_h, p_Wpack + (size_t)l * D_DIM * NPK, p_bpack + (size_t)l * NPK,
            p_delta, NPK, D_DIM, nullptr, nullptr, nullptr, p_Bm, p_Cm);
        scan_k<<<dim3(D_DIM / 8, BSZ), 128>>>(p_h, p_delta, p_Bm, p_Cm, Al_l, Dp_l,
                                              p_y, p_cnt);
        router_k<<<T_TOK / 4, 128>>>(p_y, Wr_l, br_l, p_w, p_eid, p_pos, p_cnt);
        scatter_k<<<T_TOK / 256, 256>>>(p_eid, p_pos, p_cnt, p_perm);
        gemm_tc<2, 2><<<dim3(DFF_F / 64, T_TOK / 128, E_EXP), 256>>>(
            p_y, Wu_l, bu_l, p_H, DFF_F, D_DIM,
            p_perm, nullptr, p_cnt, nullptr, nullptr);
        gemm_tc<5, 0><<<dim3(D_DIM / 64, T_TOK / 128, E_EXP * KSPL), 256>>>(
            p_H, Wo_l, nullptr, p_part, D_DIM, DFF_F / KSPL,
            p_perm, nullptr, p_cnt, nullptr, nullptr);
        ln_k<<<T_TOK, 256>>>(p_y, p_part, bo_l, p_eid, p_w, g_l, b_l, p_h,
                             (l == NLYR - 1) ? p_hH : nullptr,
                             (l == NLYR - 1) ? p_hL : nullptr);
    }

    cudaStreamWaitEvent(0, evJoin, 0);
    logits_v2<<<dim3(T_TOK / 128, V_VOC / 128), 256, LG_SMEM>>>(p_hH, p_hL, p_eH, p_eL, out);
}

// round 15
// speedup vs baseline: 1.1159x; 1.0516x over previous
#include <cuda_runtime.h>
#include <cuda_bf16.h>
#include <math.h>
#include <stdint.h>

#define T_TOK 4096
#define D_DIM 768
#define N_ST  16
#define E_EXP 4
#define DFF_F 3072
#define V_VOC 32000
#define NLYR  4
#define BSZ   2
#define SEQL  2048
#define NPK   832      // packed delta|B|C width: 768 + 16 + 16 + 32 pad
#define KSPL  4        // split-K factor for MoE down

// ---------------- scratch ----------------
__device__ float g_h[T_TOK * D_DIM];
__device__ float g_delta[T_TOK * D_DIM];
__device__ float g_Bm[T_TOK * N_ST];
__device__ float g_Cm[T_TOK * N_ST];
__device__ float g_y[T_TOK * D_DIM];
__device__ float g_part[KSPL * T_TOK * D_DIM];
__device__ float g_H[T_TOK * DFF_F];
__device__ float g_w[T_TOK];
__device__ int   g_eid[T_TOK];
__device__ int   g_pos[T_TOK];
__device__ int   g_perm[T_TOK];
__device__ int   g_cnt[E_EXP];
__device__ float g_Wpack[NLYR * D_DIM * NPK];
__device__ float g_bpack[NLYR * NPK];
__device__ __nv_bfloat16 g_eH[V_VOC * D_DIM];
__device__ __nv_bfloat16 g_eL[V_VOC * D_DIM];
__device__ __nv_bfloat16 g_hH[T_TOK * D_DIM];
__device__ __nv_bfloat16 g_hL[T_TOK * D_DIM];

// ---------------- helpers ----------------
__device__ __forceinline__ uint32_t smem_u32(const void* p) {
    uint32_t a;
    asm("{ .reg .u64 t; cvta.to.shared.u64 t, %1; cvt.u32.u64 %0, t; }" : "=r"(a) : "l"(p));
    return a;
}
__device__ __forceinline__ void cp16(uint32_t s, const void* g) {
    asm volatile("cp.async.cg.shared.global [%0], [%1], 16;" :: "r"(s), "l"(g));
}
#define CP_COMMIT() asm volatile("cp.async.commit_group;" ::: "memory")
#define CP_WAIT1()  asm volatile("cp.async.wait_group 1;" ::: "memory")
#define CP_WAIT0()  asm volatile("cp.async.wait_group 0;" ::: "memory")

#define LDSM4(R0,R1,R2,R3,ADDR) \
    asm volatile("ldmatrix.sync.aligned.m8n8.x4.shared.b16 {%0,%1,%2,%3}, [%4];" \
        : "=r"(R0),"=r"(R1),"=r"(R2),"=r"(R3) : "r"(ADDR))
#define LDSM4T(R0,R1,R2,R3,ADDR) \
    asm volatile("ldmatrix.sync.aligned.m8n8.x4.trans.shared.b16 {%0,%1,%2,%3}, [%4];" \
        : "=r"(R0),"=r"(R1),"=r"(R2),"=r"(R3) : "r"(ADDR))
#define MMA_BF16(D,AV,BV) \
    asm volatile("mma.sync.aligned.m16n8k16.row.col.f32.bf16.bf16.f32 " \
        "{%0,%1,%2,%3}, {%4,%5,%6,%7}, {%8,%9}, {%0,%1,%2,%3};" \
        : "+f"((D)[0]),"+f"((D)[1]),"+f"((D)[2]),"+f"((D)[3]) \
        : "r"((AV)[0]),"r"((AV)[1]),"r"((AV)[2]),"r"((AV)[3]), \
          "r"((BV)[0]),"r"((BV)[1]))

__device__ __forceinline__ void splt(float v, uint32_t& h, uint32_t& l) {
    __nv_bfloat16 bh = __float2bfloat16(v);
    float r = v - __bfloat162float(bh);
    __nv_bfloat16 bl = __float2bfloat16(r);
    h = (uint32_t)__bfloat16_as_ushort(bh);
    l = (uint32_t)__bfloat16_as_ushort(bl);
}
__device__ __forceinline__ void split_pack(float a, float b, uint32_t& hp, uint32_t& lp) {
    uint32_t h0, l0, h1, l1;
    splt(a, h0, l0); splt(b, h1, l1);
    hp = h0 | (h1 << 16);
    lp = l0 | (l1 << 16);
}

// ---------------- embed gather ----------------
__global__ void embed_gather_k(const int* __restrict__ x,
                               const float* __restrict__ embed,
                               float* __restrict__ h) {
    int t = blockIdx.x;
    int tok = x[t];
    const float4* src = (const float4*)(embed + (size_t)tok * D_DIM);
    float4* dst = (float4*)(h + (size_t)t * D_DIM);
    dst[threadIdx.x] = src[threadIdx.x];
}

// ---------------- fp32 -> split-bf16 planes ----------------
__global__ void split_k(const float* __restrict__ s,
                        __nv_bfloat16* __restrict__ hi,
                        __nv_bfloat16* __restrict__ lo) {
    size_t i = ((size_t)blockIdx.x * 256 + threadIdx.x) * 4;
    float4 v = *(const float4*)(s + i);
    uint32_t hp0, lp0, hp1, lp1;
    split_pack(v.x, v.y, hp0, lp0);
    split_pack(v.z, v.w, hp1, lp1);
    *(uint2*)(hi + i) = make_uint2(hp0, hp1);
    *(uint2*)(lo + i) = make_uint2(lp0, lp1);
}

// ---------------- pack [Wd|WB|WC] -> [768, 832] fp32 + biases ----------------
__global__ void pack_k(const float* __restrict__ Wd, const float* __restrict__ WB,
                       const float* __restrict__ WC,
                       const float* __restrict__ bd, const float* __restrict__ bB,
                       const float* __restrict__ bC,
                       float* __restrict__ Wp, float* __restrict__ bp) {
    int i = (blockIdx.x * 256 + threadIdx.x) * 4;
    int k = i / NPK, c = i % NPK;
#pragma unroll
    for (int j = 0; j < 4; j++) {
        int c2 = c + j;
        float v;
        if (c2 < 768)      v = Wd[k * D_DIM + c2];
        else if (c2 < 784) v = WB[k * N_ST + c2 - 768];
        else if (c2 < 800) v = WC[k * N_ST + c2 - 784];
        else               v = 0.f;
        Wp[i + j] = v;
    }
    if (blockIdx.x == 0) {
        for (int c2 = threadIdx.x; c2 < NPK; c2 += 256) {
            float v;
            if (c2 < 768)      v = bd[c2];
            else if (c2 < 784) v = bB[c2 - 768];
            else if (c2 < 800) v = bC[c2 - 784];
            else               v = 0.f;
            bp[c2] = v;
        }
    }
}

#define PA 40   // A smem pitch in bf16
#define PB 72   // B smem pitch (k-major) in bf16

// ---------------- logits GEMM v2 (proven) ----------------
#define LG_SMEM 81920

__global__ void __launch_bounds__(256, 2) logits_v2(
    const __nv_bfloat16* __restrict__ hH, const __nv_bfloat16* __restrict__ hL,
    const __nv_bfloat16* __restrict__ eH, const __nv_bfloat16* __restrict__ eL,
    float* __restrict__ out)
{
    extern __shared__ char dsm[];
    const uint32_t sb = smem_u32(dsm);
    const int tid = threadIdx.x;
    const int bm = blockIdx.x * 128;
    const int bn = blockIdx.y * 128;

    const int w = tid >> 5, lane = tid & 31;
    const int wm = (w >> 1) * 32, wn = (w & 1) * 64;

    const int lrow = tid >> 1;
    const int lsegB = (tid & 1) * 32;
    const int lsegE = (tid & 1) * 16;
    const uint32_t sRow = (uint32_t)(lrow * 80 + lsegB);

#define LG_ISSUE(C) do {                                                        \
    const int k0_ = (C) * 32;                                                   \
    const uint32_t s0_ = sb + ((C) & 1) * 40960;                                \
    const __nv_bfloat16* g_;                                                    \
    g_ = hH + (size_t)(bm + lrow) * D_DIM + k0_ + lsegE;                        \
    cp16(s0_ + sRow, g_); cp16(s0_ + sRow + 16, g_ + 8);                        \
    g_ = hL + (size_t)(bm + lrow) * D_DIM + k0_ + lsegE;                        \
    cp16(s0_ + 10240 + sRow, g_); cp16(s0_ + 10240 + sRow + 16, g_ + 8);        \
    g_ = eH + (size_t)(bn + lrow) * D_DIM + k0_ + lsegE;                        \
    cp16(s0_ + 20480 + sRow, g_); cp16(s0_ + 20480 + sRow + 16, g_ + 8);        \
    g_ = eL + (size_t)(bn + lrow) * D_DIM + k0_ + lsegE;                        \
    cp16(s0_ + 30720 + sRow, g_); cp16(s0_ + 30720 + sRow + 16, g_ + 8);        \
    CP_COMMIT(); } while (0)

    const uint32_t a_off = (uint32_t)((lane & 15) * (PA * 2) + ((lane >> 4) & 1) * 16);
    uint32_t aB[2];
#pragma unroll
    for (int mi = 0; mi < 2; mi++) aB[mi] = (uint32_t)((wm + mi * 16) * (PA * 2)) + a_off;

    const uint32_t b_off = (uint32_t)(((lane & 7) + ((lane >> 4) & 1) * 8) * (PA * 2)
                                      + ((lane >> 3) & 1) * 16);
    uint32_t bB[4];
#pragma unroll
    for (int j = 0; j < 4; j++) bB[j] = (uint32_t)((wn + j * 16) * (PA * 2)) + b_off;

    float acc[2][8][4];
#pragma unroll
    for (int mi = 0; mi < 2; mi++)
#pragma unroll
        for (int nj = 0; nj < 8; nj++)
#pragma unroll
            for (int q = 0; q < 4; q++) acc[mi][nj][q] = 0.f;

    LG_ISSUE(0);
    LG_ISSUE(1);

    const int NC = D_DIM / 32;
    for (int c = 0; c < NC; c++) {
        if (c + 1 < NC) { CP_WAIT1(); } else { CP_WAIT0(); }
        __syncthreads();
        const uint32_t base = sb + (c & 1) * 40960;
#pragma unroll
        for (int kk = 0; kk < 32; kk += 16) {
            uint32_t ah[2][4], al[2][4], bh[8][2], bl[8][2];
#pragma unroll
            for (int mi = 0; mi < 2; mi++) {
                LDSM4(ah[mi][0], ah[mi][1], ah[mi][2], ah[mi][3], base + aB[mi] + kk * 2);
                LDSM4(al[mi][0], al[mi][1], al[mi][2], al[mi][3],
                      base + 10240 + aB[mi] + kk * 2);
            }
#pragma unroll
            for (int j = 0; j < 4; j++) {
                uint32_t r0, r1, r2, r3;
                LDSM4(r0, r1, r2, r3, base + 20480 + bB[j] + kk * 2);
                bh[2 * j][0] = r0; bh[2 * j][1] = r1;
                bh[2 * j + 1][0] = r2; bh[2 * j + 1][1] = r3;
                LDSM4(r0, r1, r2, r3, base + 30720 + bB[j] + kk * 2);
                bl[2 * j][0] = r0; bl[2 * j][1] = r1;
                bl[2 * j + 1][0] = r2; bl[2 * j + 1][1] = r3;
            }
#pragma unroll
            for (int mi = 0; mi < 2; mi++)
#pragma unroll
                for (int nj = 0; nj < 8; nj++) {
                    MMA_BF16(acc[mi][nj], ah[mi], bh[nj]);
                    MMA_BF16(acc[mi][nj], ah[mi], bl[nj]);
                    MMA_BF16(acc[mi][nj], al[mi], bh[nj]);
                }
        }
        __syncthreads();
        if (c + 2 < NC) LG_ISSUE(c + 2);
    }

#pragma unroll
    for (int mi = 0; mi < 2; mi++) {
#pragma unroll
        for (int half = 0; half < 2; half++) {
            int row = bm + wm + mi * 16 + (lane >> 2) + half * 8;
            float* orow = out + (size_t)row * V_VOC + bn + wn;
#pragma unroll
            for (int nj = 0; nj < 8; nj++) {
                int col = nj * 8 + (lane & 3) * 2;
                *(float2*)(orow + col) =
                    make_float2(acc[mi][nj][half * 2], acc[mi][nj][half * 2 + 1]);
            }
        }
    }
}

// ---------------- mma.sync GEMM (in-loop split-bf16 convert) ----------------
// MODE 2: MoE up gather rows (bias+silu)
// MODE 4: fused delta|B|C: dense A, packed B (N=832), region epilogue
// MODE 5: MoE down split-K: z = e*KSPL+ks; partial out, no bias/act
template<int MODE, int ACT>
__global__ void __launch_bounds__(256) gemm_tc(
    const float* __restrict__ A, const float* __restrict__ B,
    const float* __restrict__ bias, float* __restrict__ C,
    int N, int K,
    const int* __restrict__ perm, const float* __restrict__ wsc,
    const int* __restrict__ cnt,
    float* __restrict__ BmOut, float* __restrict__ CmOut)
{
    __shared__ __align__(16) __nv_bfloat16 Ah[128 * PA], Al[128 * PA];
    __shared__ __align__(16) __nv_bfloat16 Bh[2560], Bl[2560];

    const int tid = threadIdx.x;
    const int bn = blockIdx.x * 64;
    const int bm = blockIdx.y * 128;

    int cnt_e = 0, off_e = 0, ks = 0;
    if (MODE == 2 || MODE == 5) {
        int e = (MODE == 5) ? (blockIdx.z >> 2) : blockIdx.z;
        if (MODE == 5) ks = blockIdx.z & 3;
        cnt_e = cnt[e];
        for (int q = 0; q < E_EXP; q++) if (q < e) off_e += cnt[q];
        if (bm >= cnt_e) return;
        if (MODE == 2) {
            B += (size_t)e * K * N;
            bias += (size_t)e * N;
        } else {
            B += ((size_t)e * DFF_F + (size_t)ks * (DFF_F / KSPL)) * N;
        }
    }

    const int ar = tid >> 3;
    const int ac = (tid & 7) * 4;
    const float* arow[4];
#pragma unroll
    for (int i = 0; i < 4; i++) {
        int g = bm + ar + 32 * i;
        if (MODE == 4) arow[i] = A + (size_t)g * K;
        else if (MODE == 2) arow[i] = (g < cnt_e) ? A + (size_t)perm[off_e + g] * K : nullptr;
        else arow[i] = (g < cnt_e)
            ? A + (size_t)(off_e + g) * DFF_F + (size_t)ks * (DFF_F / KSPL) : nullptr;
    }
    const int bkr = tid >> 4;
    const int bbc = (tid & 15) * 4;

    const int w = tid >> 5, lane = tid & 31;
    const int wm = (w >> 1) * 32, wn = (w & 1) * 32;
    const uint32_t sAh = (uint32_t)__cvta_generic_to_shared(Ah);
    const uint32_t sAl = (uint32_t)__cvta_generic_to_shared(Al);
    const uint32_t sBh = (uint32_t)__cvta_generic_to_shared(Bh);
    const uint32_t sBl = (uint32_t)__cvta_generic_to_shared(Bl);

    const uint32_t a_off = (uint32_t)((lane & 15) * (PA * 2) + ((lane >> 4) & 1) * 16);
    uint32_t aBase[2];
#pragma unroll
    for (int mi = 0; mi < 2; mi++)
        aBase[mi] = (uint32_t)((wm + mi * 16) * (PA * 2)) + a_off;

    uint32_t bBase[2];
    {
        uint32_t b_off = (uint32_t)((lane & 15) * (PB * 2) + ((lane >> 4) & 1) * 16);
#pragma unroll
        for (int ni2 = 0; ni2 < 2; ni2++)
            bBase[ni2] = (uint32_t)((wn + ni2 * 16) * 2) + b_off;
    }

    float acc[2][4][4];
#pragma unroll
    for (int mi = 0; mi < 2; mi++)
#pragma unroll
        for (int nj = 0; nj < 4; nj++)
#pragma unroll
            for (int q = 0; q < 4; q++) acc[mi][nj][q] = 0.f;

    float4 av[4], bv[2];

#define LOAD_G(K0) do {                                                          \
    _Pragma("unroll")                                                            \
    for (int i = 0; i < 4; i++)                                                  \
        av[i] = arow[i] ? *(const float4*)(arow[i] + (K0) + ac)                  \
                        : make_float4(0.f, 0.f, 0.f, 0.f);                       \
    _Pragma("unroll")                                                            \
    for (int i = 0; i < 2; i++)                                                  \
        bv[i] = *(const float4*)(B + (size_t)((K0) + bkr + 16 * i) * N + bn + bbc); \
    } while (0)

#define STORE_S() do {                                                           \
    _Pragma("unroll")                                                            \
    for (int i = 0; i < 4; i++) {                                                \
        int row = ar + 32 * i;                                                   \
        uint32_t h0, l0, h1, l1;                                                 \
        split_pack(av[i].x, av[i].y, h0, l0);                                    \
        split_pack(av[i].z, av[i].w, h1, l1);                                    \
        uint32_t* pH = (uint32_t*)(Ah + row * PA + ac);                          \
        uint32_t* pL = (uint32_t*)(Al + row * PA + ac);                          \
        pH[0] = h0; pH[1] = h1; pL[0] = l0; pL[1] = l1;                          \
    }                                                                            \
    _Pragma("unroll")                                                            \
    for (int i = 0; i < 2; i++) {                                                \
        uint32_t h0, l0, h1, l1;                                                 \
        split_pack(bv[i].x, bv[i].y, h0, l0);                                    \
        split_pack(bv[i].z, bv[i].w, h1, l1);                                    \
        uint32_t* pH = (uint32_t*)(Bh + (bkr + 16 * i) * PB + bbc);              \
        uint32_t* pL = (uint32_t*)(Bl + (bkr + 16 * i) * PB + bbc);              \
        pH[0] = h0; pH[1] = h1; pL[0] = l0; pL[1] = l1;                          \
    } } while (0)

    LOAD_G(0);
    for (int k0 = 0; k0 < K; k0 += 32) {
        STORE_S();
        __syncthreads();
        if (k0 + 32 < K) LOAD_G(k0 + 32);

#pragma unroll
        for (int kk = 0; kk < 32; kk += 16) {
            uint32_t ah[2][4], alr[2][4], bhf[4][2], blf[4][2];
#pragma unroll
            for (int mi = 0; mi < 2; mi++) {
                LDSM4(ah[mi][0], ah[mi][1], ah[mi][2], ah[mi][3], sAh + aBase[mi] + kk * 2);
                LDSM4(alr[mi][0], alr[mi][1], alr[mi][2], alr[mi][3], sAl + aBase[mi] + kk * 2);
            }
#pragma unroll
            for (int ni2 = 0; ni2 < 2; ni2++) {
                uint32_t r0, r1, r2, r3;
                LDSM4T(r0, r1, r2, r3, sBh + bBase[ni2] + kk * (PB * 2));
                bhf[2 * ni2][0] = r0; bhf[2 * ni2][1] = r1;
                bhf[2 * ni2 + 1][0] = r2; bhf[2 * ni2 + 1][1] = r3;
                LDSM4T(r0, r1, r2, r3, sBl + bBase[ni2] + kk * (PB * 2));
                blf[2 * ni2][0] = r0; blf[2 * ni2][1] = r1;
                blf[2 * ni2 + 1][0] = r2; blf[2 * ni2 + 1][1] = r3;
            }
#pragma unroll
            for (int mi = 0; mi < 2; mi++)
#pragma unroll
                for (int nj = 0; nj < 4; nj++) {
                    MMA_BF16(acc[mi][nj], ah[mi], bhf[nj]);
                    MMA_BF16(acc[mi][nj], ah[mi], blf[nj]);
                    MMA_BF16(acc[mi][nj], alr[mi], bhf[nj]);
                }
        }
        __syncthreads();
    }

#pragma unroll
    for (int mi = 0; mi < 2; mi++) {
#pragma unroll
        for (int half = 0; half < 2; half++) {
            int tr = wm + mi * 16 + (lane >> 2) + half * 8;
            int g = bm + tr;
            size_t orow = (size_t)g;
            bool valid = true;
            if (MODE == 2) { valid = g < cnt_e; orow = (size_t)(off_e + g); }
            else if (MODE == 5) {
                valid = g < cnt_e;
                int tok = valid ? perm[off_e + g] : 0;
                orow = (size_t)ks * T_TOK + tok;
            }
            if (!valid) continue;
#pragma unroll
            for (int nj = 0; nj < 4; nj++) {
                int col = bn + wn + nj * 8 + (lane & 3) * 2;
                float u0 = acc[mi][nj][half * 2 + 0];
                float u1 = acc[mi][nj][half * 2 + 1];
                if (MODE == 5) {
                    *(float2*)(C + orow * (size_t)N + col) = make_float2(u0, u1);
                    continue;
                }
                float2 bb = *(const float2*)&bias[col];
                u0 += bb.x; u1 += bb.y;
                if (MODE == 4) {
                    if (col < 768) {
                        u0 = fmaxf(u0, 0.f) + log1pf(expf(-fabsf(u0)));
                        u1 = fmaxf(u1, 0.f) + log1pf(expf(-fabsf(u1)));
                        *(float2*)(C + orow * (size_t)D_DIM + col) = make_float2(u0, u1);
                    } else if (col < 784) {
                        *(float2*)(BmOut + orow * (size_t)N_ST + col - 768) = make_float2(u0, u1);
                    } else if (col < 800) {
                        *(float2*)(CmOut + orow * (size_t)N_ST + col - 784) = make_float2(u0, u1);
                    }
                    continue;
                }
                if (ACT == 2) {
                    u0 = u0 / (1.f + __expf(-u0));
                    u1 = u1 / (1.f + __expf(-u1));
                }
                *(float2*)(C + orow * (size_t)N + col) = make_float2(u0, u1);
            }
        }
    }
}

// ---------------- SSM scan: deferred batched reduction (R12 grid) ----------------
// grid (D/8, B), 128 thr. Recurrence runs serially over 16 steps with pv[s]
// accumulated in registers; the 16-lane reduction for all 16 steps happens after
// (64 mutually independent shuffles pipeline at throughput). Same offset order
// (1,2,4,8) per value => bit-identical to per-step reduction.
__global__ void __launch_bounds__(128) scan_k(
    const float* __restrict__ h, const float* __restrict__ delta,
    const float* __restrict__ Bm, const float* __restrict__ Cm,
    const float* __restrict__ A_log, const float* __restrict__ Dp,
    float* __restrict__ y, int* __restrict__ cnt)
{
    const int b  = blockIdx.y;
    const int d0 = blockIdx.x * 8;
    const int tid = threadIdx.x;
    const int dg = tid >> 4;
    const int n  = tid & 15;
    const int d  = d0 + dg;

    if (blockIdx.x == 0 && b == 0 && tid < E_EXP) cnt[tid] = 0;

    const float a  = -expf(A_log[d * N_ST + n]);
    const float Dv = Dp[d];
    float hs = 0.f;

    __shared__ float xs[2][16][8], ds[2][16][8];
    __shared__ float bs[2][16][16], cs[2][16][16];

    const int lt = tid >> 3;
    const int ld = tid & 7;
    const size_t tok0 = (size_t)b * SEQL;

    xs[0][lt][ld] = h[(tok0 + lt) * D_DIM + d0 + ld];
    ds[0][lt][ld] = delta[(tok0 + lt) * D_DIM + d0 + ld];
    bs[0][lt][ld]     = Bm[(tok0 + lt) * N_ST + ld];
    bs[0][lt][ld + 8] = Bm[(tok0 + lt) * N_ST + ld + 8];
    cs[0][lt][ld]     = Cm[(tok0 + lt) * N_ST + ld];
    cs[0][lt][ld + 8] = Cm[(tok0 + lt) * N_ST + ld + 8];
    __syncthreads();

    const int NCH = SEQL / 16;
    for (int c = 0; c < NCH; c++) {
        int buf = c & 1;
        float px = 0.f, pd = 0.f, pb0 = 0.f, pb1 = 0.f, pc0 = 0.f, pc1 = 0.f;
        bool has = (c + 1) < NCH;
        if (has) {
            size_t t1 = tok0 + (c + 1) * 16 + lt;
            px = h[t1 * D_DIM + d0 + ld];
            pd = delta[t1 * D_DIM + d0 + ld];
            pb0 = Bm[t1 * N_ST + ld];  pb1 = Bm[t1 * N_ST + ld + 8];
            pc0 = Cm[t1 * N_ST + ld];  pc1 = Cm[t1 * N_ST + ld + 8];
        }
        int tbase = c * 16;

        // phase 1: pure recurrence, accumulate partial products in registers
        float pv[16];
#pragma unroll
        for (int s = 0; s < 16; s++) {
            float xv = xs[buf][s][dg];
            float dv = ds[buf][s][dg];
            float Bv = bs[buf][s][n];
            float Cv = cs[buf][s][n];
            float barA = __expf(fminf(dv * a, 2.f));
            float barB = fminf(fmaxf(dv * Bv, -2.f), 2.f);
            hs = fminf(fmaxf(fmaf(barA, hs, barB * xv), -100.f), 100.f);
            pv[s] = hs * Cv;
        }
        // phase 2: batched cross-lane reduction (independent shuffles pipeline)
#pragma unroll
        for (int o = 1; o <= 8; o <<= 1) {
#pragma unroll
            for (int s = 0; s < 16; s++)
                pv[s] += __shfl_xor_sync(0xffffffffu, pv[s], o, 16);
        }
        if (n == 0) {
#pragma unroll
            for (int s = 0; s < 16; s++)
                y[(tok0 + tbase + s) * D_DIM + d] = pv[s] + xs[buf][s][dg] * Dv;
        }

        if (has) {
            int nb = buf ^ 1;
            xs[nb][lt][ld] = px;
            ds[nb][lt][ld] = pd;
            bs[nb][lt][ld] = pb0; bs[nb][lt][ld + 8] = pb1;
            cs[nb][lt][ld] = pc0; cs[nb][lt][ld + 8] = pc1;
        }
        __syncthreads();
    }
}

// ---------------- router (top-1) + bucket ----------------
__global__ void router_k(const float* __restrict__ y,
                         const float* __restrict__ Wr, const float* __restrict__ br,
                         float* __restrict__ w, int* __restrict__ eid,
                         int* __restrict__ pos, int* __restrict__ cnt) {
    int t = blockIdx.x * 4 + (threadIdx.x >> 5);
    int lane = threadIdx.x & 31;
    float a0 = 0.f, a1 = 0.f, a2 = 0.f, a3 = 0.f;
    const float* yr = y + (size_t)t * D_DIM;
    for (int k = lane; k < D_DIM; k += 32) {
        float v = yr[k];
        float4 wr = *(const float4*)&Wr[k * 4];
        a0 = fmaf(v, wr.x, a0); a1 = fmaf(v, wr.y, a1);
        a2 = fmaf(v, wr.z, a2); a3 = fmaf(v, wr.w, a3);
    }
#pragma unroll
    for (int o = 16; o; o >>= 1) {
        a0 += __shfl_xor_sync(0xffffffffu, a0, o);
        a1 += __shfl_xor_sync(0xffffffffu, a1, o);
        a2 += __shfl_xor_sync(0xffffffffu, a2, o);
        a3 += __shfl_xor_sync(0xffffffffu, a3, o);
    }
    if (lane == 0) {
        float z[4] = {a0 + br[0], a1 + br[1], a2 + br[2], a3 + br[3]};
        int best = 0; float m = z[0];
#pragma unroll
        for (int e = 1; e < 4; e++) if (z[e] > m) { m = z[e]; best = e; }
        float s = 0.f;
#pragma unroll
        for (int e = 0; e < 4; e++) s += __expf(z[e] - m);
        w[t] = 1.f / s;
        eid[t] = best;
        pos[t] = atomicAdd(&cnt[best], 1);
    }
}

__global__ void scatter_k(const int* __restrict__ eid, const int* __restrict__ pos,
                          const int* __restrict__ cnt, int* __restrict__ perm) {
    int t = blockIdx.x * 256 + threadIdx.x;
    int e = eid[t];
    int off = 0;
#pragma unroll
    for (int q = 0; q < E_EXP; q++) if (q < e) off += cnt[q];
    perm[off + pos[t]] = t;
}

// ---------------- add + split-K reduce + layernorm ----------------
__device__ __forceinline__ float block_sum(float v, float* red) {
    int lane = threadIdx.x & 31, wid = threadIdx.x >> 5;
#pragma unroll
    for (int o = 16; o; o >>= 1) v += __shfl_xor_sync(0xffffffffu, v, o);
    if (lane == 0) red[wid] = v;
    __syncthreads();
    float r = (threadIdx.x < 8) ? red[threadIdx.x] : 0.f;
    if (wid == 0) {
#pragma unroll
        for (int o = 4; o; o >>= 1) r += __shfl_xor_sync(0xffffffffu, r, o);
        if (lane == 0) red[0] = r;
    }
    __syncthreads();
    float out = red[0];
    __syncthreads();
    return out;
}

__global__ void ln_k(const float* __restrict__ y, const float* __restrict__ part,
                     const float* __restrict__ bo, const int* __restrict__ eid,
                     const float* __restrict__ wsc,
                     const float* __restrict__ g, const float* __restrict__ b,
                     float* __restrict__ h,
                     __nv_bfloat16* __restrict__ hH, __nv_bfloat16* __restrict__ hL) {
    int t = blockIdx.x, tid = threadIdx.x;
    __shared__ float red[32];
    const float* yr = y + (size_t)t * D_DIM;
    const float* pr = part + (size_t)t * D_DIM;
    const int e = eid[t];
    const float wv = wsc[t];
    const float* bo_e = bo + (size_t)e * D_DIM;
    float o[3];
    float s = 0.f;
#pragma unroll
    for (int i = 0; i < 3; i++) {
        int idx = tid + i * 256;
        float m = pr[idx];
#pragma unroll
        for (int ksl = 1; ksl < KSPL; ksl++)
            m += pr[(size_t)ksl * T_TOK * D_DIM + idx];
        m = (m + bo_e[idx]) * wv;
        o[i] = yr[idx] + m;
        s += o[i];
    }
    s = block_sum(s, red);
    float mu = s * (1.f / D_DIM);
    float sq = 0.f;
#pragma unroll
    for (int i = 0; i < 3; i++) { float d = o[i] - mu; sq += d * d; }
    sq = block_sum(sq, red);
    float inv = rsqrtf(sq * (1.f / D_DIM) + 1e-5f);
#pragma unroll
    for (int i = 0; i < 3; i++) {
        int idx = tid + i * 256;
        float val = (o[i] - mu) * inv * g[idx] + b[idx];
        size_t oi = (size_t)t * D_DIM + idx;
        h[oi] = val;
        if (hH) {
            __nv_bfloat16 hb = __float2bfloat16(val);
            hH[oi] = hb;
            hL[oi] = __float2bfloat16(val - __bfloat162float(hb));
        }
    }
}

// ---------------- launcher ----------------
extern "C" void kernel_launch(void* const* d_in, const int* in_sizes, int n_in,
                              void* d_out, int out_size) {
    (void)in_sizes; (void)n_in; (void)out_size;
    const int*   x     = (const int*)  d_in[0];
    const float* embed = (const float*)d_in[1];
    const float* A_log = (const float*)d_in[2];
    const float* Dp    = (const float*)d_in[3];
    const float* Wd    = (const float*)d_in[4];
    const float* bd    = (const float*)d_in[5];
    const float* WB    = (const float*)d_in[6];
    const float* bB    = (const float*)d_in[7];
    const float* WC    = (const float*)d_in[8];
    const float* bC    = (const float*)d_in[9];
    const float* Wr    = (const float*)d_in[10];
    const float* br    = (const float*)d_in[11];
    const float* Wu    = (const float*)d_in[12];
    const float* bu    = (const float*)d_in[13];
    const float* Wo    = (const float*)d_in[14];
    const float* bo    = (const float*)d_in[15];
    const float* lng   = (const float*)d_in[16];
    const float* lnb   = (const float*)d_in[17];
    float* out = (float*)d_out;

    float *p_h, *p_delta, *p_Bm, *p_Cm, *p_y, *p_part, *p_H, *p_w, *p_Wpack, *p_bpack;
    int *p_eid, *p_pos, *p_perm, *p_cnt;
    __nv_bfloat16 *p_eH, *p_eL, *p_hH, *p_hL;
    cudaGetSymbolAddress((void**)&p_h, g_h);
    cudaGetSymbolAddress((void**)&p_delta, g_delta);
    cudaGetSymbolAddress((void**)&p_Bm, g_Bm);
    cudaGetSymbolAddress((void**)&p_Cm, g_Cm);
    cudaGetSymbolAddress((void**)&p_y, g_y);
    cudaGetSymbolAddress((void**)&p_part, g_part);
    cudaGetSymbolAddress((void**)&p_H, g_H);
    cudaGetSymbolAddress((void**)&p_w, g_w);
    cudaGetSymbolAddress((void**)&p_Wpack, g_Wpack);
    cudaGetSymbolAddress((void**)&p_bpack, g_bpack);
    cudaGetSymbolAddress((void**)&p_eid, g_eid);
    cudaGetSymbolAddress((void**)&p_pos, g_pos);
    cudaGetSymbolAddress((void**)&p_perm, g_perm);
    cudaGetSymbolAddress((void**)&p_cnt, g_cnt);
    cudaGetSymbolAddress((void**)&p_eH, g_eH);
    cudaGetSymbolAddress((void**)&p_eL, g_eL);
    cudaGetSymbolAddress((void**)&p_hH, g_hH);
    cudaGetSymbolAddress((void**)&p_hL, g_hL);

    cudaFuncSetAttribute(logits_v2, cudaFuncAttributeMaxDynamicSharedMemorySize, LG_SMEM);

    // side stream: all 4 layer packs (needed from layer 0) then embed split (needed last)
    static cudaStream_t s2 = nullptr;
    static cudaEvent_t evFork = nullptr, evPack = nullptr, evJoin = nullptr;
    if (!s2) {
        cudaStreamCreateWithFlags(&s2, cudaStreamNonBlocking);
        cudaEventCreateWithFlags(&evFork, cudaEventDisableTiming);
        cudaEventCreateWithFlags(&evPack, cudaEventDisableTiming);
        cudaEventCreateWithFlags(&evJoin, cudaEventDisableTiming);
    }
    cudaEventRecord(evFork, 0);
    cudaStreamWaitEvent(s2, evFork, 0);
    for (int l = 0; l < NLYR; l++) {
        pack_k<<<D_DIM * NPK / 1024, 256, 0, s2>>>(
            Wd + (size_t)l * D_DIM * D_DIM,
            WB + (size_t)l * D_DIM * N_ST, WC + (size_t)l * D_DIM * N_ST,
            bd + (size_t)l * D_DIM, bB + (size_t)l * N_ST, bC + (size_t)l * N_ST,
            p_Wpack + (size_t)l * D_DIM * NPK, p_bpack + (size_t)l * NPK);
    }
    cudaEventRecord(evPack, s2);
    split_k<<<V_VOC * D_DIM / 1024, 256, 0, s2>>>(embed, p_eH, p_eL);
    cudaEventRecord(evJoin, s2);

    embed_gather_k<<<T_TOK, 192>>>(x, embed, p_h);
    cudaStreamWaitEvent(0, evPack, 0);   // all packed weights ready

    for (int l = 0; l < NLYR; l++) {
        const float* Al_l = A_log + (size_t)l * D_DIM * N_ST;
        const float* Dp_l = Dp + (size_t)l * D_DIM;
        const float* Wr_l = Wr + (size_t)l * D_DIM * E_EXP;
        const float* br_l = br + (size_t)l * E_EXP;
        const float* Wu_l = Wu + (size_t)l * E_EXP * D_DIM * DFF_F;
        const float* bu_l = bu + (size_t)l * E_EXP * DFF_F;
        const float* Wo_l = Wo + (size_t)l * E_EXP * DFF_F * D_DIM;
        const float* bo_l = bo + (size_t)l * E_EXP * D_DIM;
        const float* g_l  = lng + (size_t)l * D_DIM;
        const float* b_l  = lnb + (size_t)l * D_DIM;

        gemm_tc<4, 1><<<dim3(NPK / 64, T_TOK / 128), 256>>>(
            p_h, p_Wpack + (size_t)l * D_DIM * NPK, p_bpack + (size_t)l * NPK,
            p_delta, NPK, D_DIM, nullptr, nullptr, nullptr, p_Bm, p_Cm);
        scan_k<<<dim3(D_DIM / 8, BSZ), 128>>>(p_h, p_delta, p_Bm, p_Cm, Al_l, Dp_l,
                                              p_y, p_cnt);
        router_k<<<T_TOK / 4, 128>>>(p_y, Wr_l, br_l, p_w, p_eid, p_pos, p_cnt);
        scatter_k<<<T_TOK / 256, 256>>>(p_eid, p_pos, p_cnt, p_perm);
        gemm_tc<2, 2><<<dim3(DFF_F / 64, T_TOK / 128, E_EXP), 256>>>(
            p_y, Wu_l, bu_l, p_H, DFF_F, D_DIM,
            p_perm, nullptr, p_cnt, nullptr, nullptr);
        gemm_tc<5, 0><<<dim3(D_DIM / 64, T_TOK / 128, E_EXP * KSPL), 256>>>(
            p_H, Wo_l, nullptr, p_part, D_DIM, DFF_F / KSPL,
            p_perm, nullptr, p_cnt, nullptr, nullptr);
        ln_k<<<T_TOK, 256>>>(p_y, p_part, bo_l, p_eid, p_w, g_l, b_l, p_h,
                             (l == NLYR - 1) ? p_hH : nullptr,
                             (l == NLYR - 1) ? p_hL : nullptr);
    }

    cudaStreamWaitEvent(0, evJoin, 0);
    logits_v2<<<dim3(T_TOK / 128, V_VOC / 128), 256, LG_SMEM>>>(p_hH, p_hL, p_eH, p_eL, out);
}